// round 10
// baseline (speedup 1.0000x reference)
#include <cuda_runtime.h>
#include <cuda_fp16.h>
#include <math.h>
#include <stdint.h>

#define NN   262144
#define HH   256
#define NV   65536
#define NG   512
#define NP   8
#define NHID 64

#define NTILES    4096      // NN / 64
#define GRID_MAIN 148

// ---------------- device globals ----------------
__device__ float  g_sums[NG * HH];
__device__ float  g_maxs[NG * HH];
__device__ int    g_start[NG + 1];

// ---------------- helpers ----------------
__device__ __forceinline__ uint32_t smem_u32(const void* p) {
    uint32_t a;
    asm("{ .reg .u64 t; cvta.to.shared.u64 t, %1; cvt.u32.u64 %0, t; }" : "=r"(a) : "l"(p));
    return a;
}
__device__ __forceinline__ void atomicMaxF(float* addr, float v) {
    if (v >= 0.0f) atomicMax((int*)addr, __float_as_int(v));
    else           atomicMin((unsigned int*)addr, __float_as_uint(v));
}
#define LDMX4(r0,r1,r2,r3,addr) \
    asm volatile("ldmatrix.sync.aligned.m8n8.x4.shared.b16 {%0,%1,%2,%3}, [%4];" \
                 : "=r"(r0), "=r"(r1), "=r"(r2), "=r"(r3) : "r"(addr))
#define MMA16816(c0,c1,c2,c3,a0,a1,a2,a3,b0,b1) \
    asm volatile("mma.sync.aligned.m16n8k16.row.col.f32.f16.f16.f32 " \
                 "{%0,%1,%2,%3}, {%4,%5,%6,%7}, {%8,%9}, {%0,%1,%2,%3};" \
                 : "+f"(c0), "+f"(c1), "+f"(c2), "+f"(c3) \
                 : "r"(a0), "r"(a1), "r"(a2), "r"(a3), "r"(b0), "r"(b1))

// ---------------- main: persistent HMMA GEMM; prep fully absorbed ----------------
// smem layout (206848 B dynamic):
//   B:        [0, 135168)                256 rows x 264 halfs (stride 528 B)
//   A stages: [135168, 135168+2*33792)   2 x (64 rows x 264 halfs)
//   misc at 202752:
//     brow[2][64] int (512) | wrow[2][64] f (512) | sbias[256] f (1024) | sgate[448] f (1792)
#define A_OFF    135168
#define A_STAGE  33792
#define MISC_OFF 202752
#define SMEM_SZ  206848

__global__ __launch_bounds__(512, 1) void main_kernel(
    const float* __restrict__ emb,
    const int*   __restrict__ batch,
    const int*   __restrict__ ntype,
    const float* __restrict__ bpre,
    const float* __restrict__ Wpre,
    const float* __restrict__ props,
    const float* __restrict__ W1, const float* __restrict__ b1,
    const float* __restrict__ W2, const float* __restrict__ b2)
{
    extern __shared__ char sm[];
    const uint32_t sbase = smem_u32(sm);
    int*   brow  = (int*)  (sm + MISC_OFF);            // [2][64]
    float* wrow  = (float*)(sm + MISC_OFF + 512);      // [2][64]
    float* sbias = (float*)(sm + MISC_OFF + 1024);     // [256]
    float* sgate = (float*)(sm + MISC_OFF + 2048);     // [448]

    const int tid  = threadIdx.x;
    const int wid  = tid >> 5;
    const int lane = tid & 31;
    const int wm   = wid >> 2;     // 0..3: rows [wm*16, +16)
    const int wn   = wid & 3;      // 0..3: cols [wn*64, +64)
    const int t0   = blockIdx.x;

    // ---- phase A: B transpose+convert, gates, g_start scan, sbias, A(t0) LDG ----

    // B: Wpre[k][n] -> Bs[n][k] fp16 (coalesced LDG.32 across n at fixed k)
    {
        const int bn  = tid & 255;       // output row n
        const int bk0 = (tid >> 8) * 128;
        const uint32_t bdst = sbase + (uint32_t)(bn * 528 + bk0 * 2);
        #pragma unroll
        for (int jj = 0; jj < 16; jj++) {
            float v[8];
            #pragma unroll
            for (int i = 0; i < 8; i++)
                v[i] = __ldg(&Wpre[(size_t)(bk0 + jj * 8 + i) * 256 + bn]);
            __half2 q0 = __float22half2_rn(make_float2(v[0], v[1]));
            __half2 q1 = __float22half2_rn(make_float2(v[2], v[3]));
            __half2 q2 = __float22half2_rn(make_float2(v[4], v[5]));
            __half2 q3 = __float22half2_rn(make_float2(v[6], v[7]));
            asm volatile("st.shared.v4.b32 [%0], {%1,%2,%3,%4};"
                         :: "r"(bdst + jj * 16),
                            "r"(*(uint32_t*)&q0), "r"(*(uint32_t*)&q1),
                            "r"(*(uint32_t*)&q2), "r"(*(uint32_t*)&q3) : "memory");
        }
    }

    // gates for this CTA's tiles only
    {
        const int nt_cta = (NTILES - 1 - t0) / GRID_MAIN + 1;   // 27 or 28
        if (tid < nt_cta * 16) {
            const int j = tid >> 4, r = tid & 15;
            const int var = (t0 + j * GRID_MAIN) * 16 + r;
            float4 p0 = __ldg((const float4*)props + var * 2);
            float4 p1 = __ldg((const float4*)props + var * 2 + 1);
            float pr[NP] = {p0.x, p0.y, p0.z, p0.w, p1.x, p1.y, p1.z, p1.w};
            float accA = __ldg(b2), accB = 0.0f;
            #pragma unroll
            for (int jh = 0; jh < NHID; jh += 4) {
                float s0 = __ldg(b1 + jh),     s1 = __ldg(b1 + jh + 1);
                float s2 = __ldg(b1 + jh + 2), s3 = __ldg(b1 + jh + 3);
                #pragma unroll
                for (int p = 0; p < NP; p++) {
                    float pv = pr[p];
                    const float* w = W1 + p * NHID + jh;
                    s0 = fmaf(pv, __ldg(w),     s0);
                    s1 = fmaf(pv, __ldg(w + 1), s1);
                    s2 = fmaf(pv, __ldg(w + 2), s2);
                    s3 = fmaf(pv, __ldg(w + 3), s3);
                }
                accA = fmaf(fmaxf(s0, 0.0f), __ldg(W2 + jh),     accA);
                accB = fmaf(fmaxf(s1, 0.0f), __ldg(W2 + jh + 1), accB);
                accA = fmaf(fmaxf(s2, 0.0f), __ldg(W2 + jh + 2), accA);
                accB = fmaf(fmaxf(s3, 0.0f), __ldg(W2 + jh + 3), accB);
            }
            sgate[tid] = 1.0f / (1.0f + expf(-(accA + accB)));
        }
    }

    // segment boundary scan (first 65536 global threads, 4 nodes each)
    {
        int gid = t0 * 512 + tid;
        if (gid < NN / 4) {
            int i0 = gid * 4;
            int4 b4 = *(const int4*)&batch[i0];
            int v[4] = {b4.x, b4.y, b4.z, b4.w};
            int p = (i0 == 0) ? -1 : __ldg(&batch[i0 - 1]);
            #pragma unroll
            for (int e = 0; e < 4; e++) {
                for (int g = p + 1; g <= v[e]; g++) g_start[g] = i0 + e;
                p = v[e];
            }
            if (i0 + 4 == NN)
                for (int g = v[3] + 1; g <= NG; g++) g_start[g] = NN;
        }
    }

    if (tid < 256) sbias[tid] = bpre[tid];

    const int arow = tid >> 3;     // 0..63
    const int aseg = tid & 7;      // float4 slot
    const uint32_t a_sts0 = sbase + A_OFF + (uint32_t)((arow * 264 + aseg * 4) * 2);

    float4 ra[8];
    {
        const float* ap = emb + (size_t)(t0 * 64 + arow) * HH + aseg * 4;
        #pragma unroll
        for (int j = 0; j < 8; j++) ra[j] = *(const float4*)(ap + j * 32);
    }
    __syncthreads();

    // ---- phase B: A(t0) STS, brow/wrow(t0) (needs sgate) ----
    {
        #pragma unroll
        for (int j = 0; j < 8; j++) {
            __half2 h0 = __float22half2_rn(make_float2(ra[j].x, ra[j].y));
            __half2 h1 = __float22half2_rn(make_float2(ra[j].z, ra[j].w));
            asm volatile("st.shared.v2.b32 [%0], {%1,%2};"
                         :: "r"(a_sts0 + j * 64),
                            "r"(*(uint32_t*)&h0), "r"(*(uint32_t*)&h1) : "memory");
        }
    }
    if (tid < 64) {
        int m = t0 * 64 + tid;
        brow[tid] = batch[m];
        wrow[tid] = (ntype[m] == 0) ? sgate[tid >> 2] : 1.0f;
    }
    __syncthreads();

    // ldmatrix lane addresses (stride 264 halfs -> conflict-free)
    const uint32_t a_lm = sbase + A_OFF +
        (uint32_t)(((wm * 16 + (lane & 15)) * 264 + (lane >> 4) * 8) * 2);
    const uint32_t b_lm = sbase +
        (uint32_t)(((wn * 64 + (lane >> 4) * 8 + (lane & 7)) * 264 + ((lane >> 3) & 1) * 8) * 2);

    for (int t = t0, it = 0; t < NTILES; t += GRID_MAIN, it++) {
        const int cur = it & 1;
        const int nt  = t + GRID_MAIN;
        const bool hn = (nt < NTILES);

        if (hn) {
            const float* ap = emb + (size_t)(nt * 64 + arow) * HH + aseg * 4;
            #pragma unroll
            for (int j = 0; j < 8; j++) ra[j] = *(const float4*)(ap + j * 32);
            if (tid < 64) {
                int m = nt * 64 + tid;
                brow[(cur ^ 1) * 64 + tid] = batch[m];
                wrow[(cur ^ 1) * 64 + tid] =
                    (ntype[m] == 0) ? sgate[(it + 1) * 16 + (tid >> 2)] : 1.0f;
            }
        }

        float acc[8][4];
        #pragma unroll
        for (int ni = 0; ni < 8; ni++)
            #pragma unroll
            for (int r = 0; r < 4; r++) acc[ni][r] = 0.0f;

        const uint32_t ab = a_lm + (uint32_t)(cur * A_STAGE);
        #pragma unroll
        for (int ks = 0; ks < 16; ks++) {
            uint32_t af[4];
            LDMX4(af[0], af[1], af[2], af[3], ab + ks * 32);
            uint32_t bf[4][4];
            #pragma unroll
            for (int nip = 0; nip < 4; nip++)
                LDMX4(bf[nip][0], bf[nip][1], bf[nip][2], bf[nip][3],
                      b_lm + nip * 8448 + ks * 32);
            #pragma unroll
            for (int ni = 0; ni < 8; ni++)
                MMA16816(acc[ni][0], acc[ni][1], acc[ni][2], acc[ni][3],
                         af[0], af[1], af[2], af[3],
                         bf[ni >> 1][(ni & 1) * 2], bf[ni >> 1][(ni & 1) * 2 + 1]);
        }

        if (hn) {
            uint32_t base = sbase + A_OFF + (uint32_t)((cur ^ 1) * A_STAGE)
                          + (uint32_t)((arow * 264 + aseg * 4) * 2);
            #pragma unroll
            for (int j = 0; j < 8; j++) {
                __half2 h0 = __float22half2_rn(make_float2(ra[j].x, ra[j].y));
                __half2 h1 = __float22half2_rn(make_float2(ra[j].z, ra[j].w));
                asm volatile("st.shared.v2.b32 [%0], {%1,%2};"
                             :: "r"(base + j * 64),
                                "r"(*(uint32_t*)&h0), "r"(*(uint32_t*)&h1) : "memory");
            }
        }

        // ---- epilogue: bias + gate, shuffle segment-reduce, atomics ----
        {
            const int l1 = wm * 16 + (lane >> 2);
            const int l2 = l1 + 8;
            const int*   br = brow + cur * 64;
            const float* wr = wrow + cur * 64;
            const float w1 = wr[l1], w2 = wr[l2];
            #pragma unroll
            for (int ni = 0; ni < 8; ni++) {
                int c = wn * 64 + ni * 8 + (lane & 3) * 2;
                float b0 = sbias[c], b1 = sbias[c + 1];
                acc[ni][0] = (acc[ni][0] + b0) * w1;
                acc[ni][1] = (acc[ni][1] + b1) * w1;
                acc[ni][2] = (acc[ni][2] + b0) * w2;
                acc[ni][3] = (acc[ni][3] + b1) * w2;
            }
            const int glo = br[wm * 16], ghi = br[wm * 16 + 15];
            const int bg1 = br[l1], bg2 = br[l2];
            for (int g = glo; g <= ghi; g++) {
                const bool p1 = (bg1 == g), p2 = (bg2 == g);
                #pragma unroll
                for (int ni = 0; ni < 8; ni++) {
                    float s0 = (p1 ? acc[ni][0] : 0.0f) + (p2 ? acc[ni][2] : 0.0f);
                    float s1 = (p1 ? acc[ni][1] : 0.0f) + (p2 ? acc[ni][3] : 0.0f);
                    float m0v = fmaxf(p1 ? acc[ni][0] : -INFINITY, p2 ? acc[ni][2] : -INFINITY);
                    float m1v = fmaxf(p1 ? acc[ni][1] : -INFINITY, p2 ? acc[ni][3] : -INFINITY);
                    #pragma unroll
                    for (int off = 4; off < 32; off <<= 1) {
                        s0  += __shfl_xor_sync(0xffffffffu, s0,  off);
                        s1  += __shfl_xor_sync(0xffffffffu, s1,  off);
                        m0v = fmaxf(m0v, __shfl_xor_sync(0xffffffffu, m0v, off));
                        m1v = fmaxf(m1v, __shfl_xor_sync(0xffffffffu, m1v, off));
                    }
                    if (lane < 4) {
                        int c = wn * 64 + ni * 8 + lane * 2;
                        atomicAdd(&g_sums[g * HH + c],     s0);
                        atomicAdd(&g_sums[g * HH + c + 1], s1);
                        if (m0v > -INFINITY) atomicMaxF(&g_maxs[g * HH + c],     m0v);
                        if (m1v > -INFINITY) atomicMaxF(&g_maxs[g * HH + c + 1], m1v);
                    }
                }
            }
        }
        __syncthreads();
    }
}

// ---------------- final linear: k-unrolled, MLP-8 load batching ----------------
__global__ __launch_bounds__(256) void final_kernel(
    const float* __restrict__ Wpost,
    const float* __restrict__ bpost,
    float* __restrict__ out)
{
    __shared__ float comb[8][2 * HH];
    __shared__ float invc[8];
    int tid = threadIdx.x;
    int g0 = blockIdx.x * 8;

    if (tid < 8) {
        int g = g0 + tid;
        int c = g_start[g + 1] - g_start[g];
        invc[tid] = 1.0f / fmaxf((float)c, 1.0f);
    }
    __syncthreads();

    for (int idx = tid; idx < 8 * 2 * HH; idx += 256) {
        int g = idx >> 9;
        int k = idx & 511;
        float v;
        if (k < HH) {
            v = g_sums[(size_t)(g0 + g) * HH + k] * invc[g];
        } else {
            float m = g_maxs[(size_t)(g0 + g) * HH + (k - HH)];
            v = isfinite(m) ? m : 0.0f;
        }
        comb[g][k] = v;
    }
    __syncthreads();

    float acc[8];
    #pragma unroll
    for (int g = 0; g < 8; g++) acc[g] = 0.0f;

    // k-loop unrolled x8: 8 independent Wpost loads in flight per group
    for (int k0 = 0; k0 < 2 * HH; k0 += 8) {
        float wv[8];
        #pragma unroll
        for (int u = 0; u < 8; u++)
            wv[u] = __ldg(&Wpost[(size_t)(k0 + u) * HH + tid]);
        #pragma unroll
        for (int u = 0; u < 8; u++) {
            #pragma unroll
            for (int g = 0; g < 8; g++)
                acc[g] = fmaf(comb[g][k0 + u], wv[u], acc[g]);
        }
    }
    float bb = bpost[tid];
    #pragma unroll
    for (int g = 0; g < 8; g++)
        out[(size_t)(g0 + g) * HH + tid] = acc[g] + bb;
}

// ---------------- launch ----------------
extern "C" void kernel_launch(void* const* d_in, const int* in_sizes, int n_in,
                              void* d_out, int out_size)
{
    const float* emb   = (const float*)d_in[0];
    const int*   batch = (const int*)  d_in[1];
    const float* props = (const float*)d_in[2];
    const int*   ntype = (const int*)  d_in[3];
    const float* Wpre  = (const float*)d_in[4];
    const float* bpre  = (const float*)d_in[5];
    const float* W1    = (const float*)d_in[6];
    const float* b1    = (const float*)d_in[7];
    const float* W2    = (const float*)d_in[8];
    const float* b2    = (const float*)d_in[9];
    const float* Wpost = (const float*)d_in[10];
    const float* bpost = (const float*)d_in[11];
    float* out = (float*)d_out;

    cudaFuncSetAttribute(main_kernel, cudaFuncAttributeMaxDynamicSharedMemorySize, SMEM_SZ);

    void* p_sums = nullptr;
    void* p_maxs = nullptr;
    cudaGetSymbolAddress(&p_sums, g_sums);
    cudaGetSymbolAddress(&p_maxs, g_maxs);
    cudaMemsetAsync(p_sums, 0x00, NG * HH * sizeof(float));
    cudaMemsetAsync(p_maxs, 0xFF, NG * HH * sizeof(float));   // NaN -> acts as -inf for our atomics

    main_kernel<<<GRID_MAIN, 512, SMEM_SZ>>>(emb, batch, ntype, bpre, Wpre,
                                             props, W1, b1, W2, b2);
    final_kernel<<<NG / 8, 256>>>(Wpost, bpost, out);
}

// round 11
// speedup vs baseline: 1.0134x; 1.0134x over previous
#include <cuda_runtime.h>
#include <cuda_fp16.h>
#include <math.h>
#include <stdint.h>

#define NN   262144
#define HH   256
#define NV   65536
#define NG   512
#define NP   8
#define NHID 64

#define NTILES    4096      // NN / 64
#define GRID_MAIN 148

// ---------------- device globals ----------------
__device__ float  g_sums[NG * HH];
__device__ float  g_maxs[NG * HH];
__device__ int    g_start[NG + 1];

// ---------------- helpers ----------------
__device__ __forceinline__ uint32_t smem_u32(const void* p) {
    uint32_t a;
    asm("{ .reg .u64 t; cvta.to.shared.u64 t, %1; cvt.u32.u64 %0, t; }" : "=r"(a) : "l"(p));
    return a;
}
__device__ __forceinline__ void atomicMaxF(float* addr, float v) {
    if (v >= 0.0f) atomicMax((int*)addr, __float_as_int(v));
    else           atomicMin((unsigned int*)addr, __float_as_uint(v));
}
#define LDMX4(r0,r1,r2,r3,addr) \
    asm volatile("ldmatrix.sync.aligned.m8n8.x4.shared.b16 {%0,%1,%2,%3}, [%4];" \
                 : "=r"(r0), "=r"(r1), "=r"(r2), "=r"(r3) : "r"(addr))
#define MMA16816(c0,c1,c2,c3,a0,a1,a2,a3,b0,b1) \
    asm volatile("mma.sync.aligned.m16n8k16.row.col.f32.f16.f16.f32 " \
                 "{%0,%1,%2,%3}, {%4,%5,%6,%7}, {%8,%9}, {%0,%1,%2,%3};" \
                 : "+f"(c0), "+f"(c1), "+f"(c2), "+f"(c3) \
                 : "r"(a0), "r"(a1), "r"(a2), "r"(a3), "r"(b0), "r"(b1))

// ---------------- main: persistent HMMA GEMM; prep fully absorbed ----------------
// smem layout (206848 B dynamic):
//   B:        [0, 135168)                256 rows x 264 halfs (stride 528 B)
//   A stages: [135168, 135168+2*33792)   2 x (64 rows x 264 halfs)
//   misc at 202752:
//     brow[2][64] int (512) | wrow[2][64] f (512) | sbias[256] f (1024) | sgate[448] f (1792)
#define A_OFF    135168
#define A_STAGE  33792
#define MISC_OFF 202752
#define SMEM_SZ  206848

__global__ __launch_bounds__(512, 1) void main_kernel(
    const float* __restrict__ emb,
    const int*   __restrict__ batch,
    const int*   __restrict__ ntype,
    const float* __restrict__ bpre,
    const float* __restrict__ Wpre,
    const float* __restrict__ props,
    const float* __restrict__ W1, const float* __restrict__ b1,
    const float* __restrict__ W2, const float* __restrict__ b2)
{
    extern __shared__ char sm[];
    const uint32_t sbase = smem_u32(sm);
    int*   brow  = (int*)  (sm + MISC_OFF);            // [2][64]
    float* wrow  = (float*)(sm + MISC_OFF + 512);      // [2][64]
    float* sbias = (float*)(sm + MISC_OFF + 1024);     // [256]
    float* sgate = (float*)(sm + MISC_OFF + 2048);     // [448]

    const int tid  = threadIdx.x;
    const int wid  = tid >> 5;
    const int lane = tid & 31;
    const int wm   = wid >> 2;     // 0..3: rows [wm*16, +16)
    const int wn   = wid & 3;      // 0..3: cols [wn*64, +64)
    const int t0   = blockIdx.x;

    // ---- phase A: B transpose+convert, gates, g_start scan, sbias, A(t0) LDG ----

    // B: Wpre[k][n] -> Bs[n][k] fp16 (coalesced LDG.32 across n at fixed k)
    {
        const int bn  = tid & 255;       // output row n
        const int bk0 = (tid >> 8) * 128;
        const uint32_t bdst = sbase + (uint32_t)(bn * 528 + bk0 * 2);
        #pragma unroll
        for (int jj = 0; jj < 16; jj++) {
            float v[8];
            #pragma unroll
            for (int i = 0; i < 8; i++)
                v[i] = __ldg(&Wpre[(size_t)(bk0 + jj * 8 + i) * 256 + bn]);
            __half2 q0 = __float22half2_rn(make_float2(v[0], v[1]));
            __half2 q1 = __float22half2_rn(make_float2(v[2], v[3]));
            __half2 q2 = __float22half2_rn(make_float2(v[4], v[5]));
            __half2 q3 = __float22half2_rn(make_float2(v[6], v[7]));
            asm volatile("st.shared.v4.b32 [%0], {%1,%2,%3,%4};"
                         :: "r"(bdst + jj * 16),
                            "r"(*(uint32_t*)&q0), "r"(*(uint32_t*)&q1),
                            "r"(*(uint32_t*)&q2), "r"(*(uint32_t*)&q3) : "memory");
        }
    }

    // gates for this CTA's tiles only
    {
        const int nt_cta = (NTILES - 1 - t0) / GRID_MAIN + 1;   // 27 or 28
        if (tid < nt_cta * 16) {
            const int j = tid >> 4, r = tid & 15;
            const int var = (t0 + j * GRID_MAIN) * 16 + r;
            float4 p0 = __ldg((const float4*)props + var * 2);
            float4 p1 = __ldg((const float4*)props + var * 2 + 1);
            float pr[NP] = {p0.x, p0.y, p0.z, p0.w, p1.x, p1.y, p1.z, p1.w};
            float accA = __ldg(b2), accB = 0.0f;
            #pragma unroll
            for (int jh = 0; jh < NHID; jh += 4) {
                float s0 = __ldg(b1 + jh),     s1 = __ldg(b1 + jh + 1);
                float s2 = __ldg(b1 + jh + 2), s3 = __ldg(b1 + jh + 3);
                #pragma unroll
                for (int p = 0; p < NP; p++) {
                    float pv = pr[p];
                    const float* w = W1 + p * NHID + jh;
                    s0 = fmaf(pv, __ldg(w),     s0);
                    s1 = fmaf(pv, __ldg(w + 1), s1);
                    s2 = fmaf(pv, __ldg(w + 2), s2);
                    s3 = fmaf(pv, __ldg(w + 3), s3);
                }
                accA = fmaf(fmaxf(s0, 0.0f), __ldg(W2 + jh),     accA);
                accB = fmaf(fmaxf(s1, 0.0f), __ldg(W2 + jh + 1), accB);
                accA = fmaf(fmaxf(s2, 0.0f), __ldg(W2 + jh + 2), accA);
                accB = fmaf(fmaxf(s3, 0.0f), __ldg(W2 + jh + 3), accB);
            }
            sgate[tid] = 1.0f / (1.0f + expf(-(accA + accB)));
        }
    }

    // segment boundary scan (first 65536 global threads, 4 nodes each)
    {
        int gid = t0 * 512 + tid;
        if (gid < NN / 4) {
            int i0 = gid * 4;
            int4 b4 = *(const int4*)&batch[i0];
            int v[4] = {b4.x, b4.y, b4.z, b4.w};
            int p = (i0 == 0) ? -1 : __ldg(&batch[i0 - 1]);
            #pragma unroll
            for (int e = 0; e < 4; e++) {
                for (int g = p + 1; g <= v[e]; g++) g_start[g] = i0 + e;
                p = v[e];
            }
            if (i0 + 4 == NN)
                for (int g = v[3] + 1; g <= NG; g++) g_start[g] = NN;
        }
    }

    if (tid < 256) sbias[tid] = bpre[tid];

    const int arow = tid >> 3;     // 0..63
    const int aseg = tid & 7;      // float4 slot
    const uint32_t a_sts0 = sbase + A_OFF + (uint32_t)((arow * 264 + aseg * 4) * 2);

    float4 ra[8];
    {
        const float* ap = emb + (size_t)(t0 * 64 + arow) * HH + aseg * 4;
        #pragma unroll
        for (int j = 0; j < 8; j++) ra[j] = *(const float4*)(ap + j * 32);
    }
    __syncthreads();

    // ---- phase B: A(t0) STS, brow/wrow(t0) (needs sgate) ----
    {
        #pragma unroll
        for (int j = 0; j < 8; j++) {
            __half2 h0 = __float22half2_rn(make_float2(ra[j].x, ra[j].y));
            __half2 h1 = __float22half2_rn(make_float2(ra[j].z, ra[j].w));
            asm volatile("st.shared.v2.b32 [%0], {%1,%2};"
                         :: "r"(a_sts0 + j * 64),
                            "r"(*(uint32_t*)&h0), "r"(*(uint32_t*)&h1) : "memory");
        }
    }
    if (tid < 64) {
        int m = t0 * 64 + tid;
        brow[tid] = batch[m];
        wrow[tid] = (ntype[m] == 0) ? sgate[tid >> 2] : 1.0f;
    }
    __syncthreads();

    // ldmatrix lane addresses (stride 264 halfs -> conflict-free)
    const uint32_t a_lm = sbase + A_OFF +
        (uint32_t)(((wm * 16 + (lane & 15)) * 264 + (lane >> 4) * 8) * 2);
    const uint32_t b_lm = sbase +
        (uint32_t)(((wn * 64 + (lane >> 4) * 8 + (lane & 7)) * 264 + ((lane >> 3) & 1) * 8) * 2);

    for (int t = t0, it = 0; t < NTILES; t += GRID_MAIN, it++) {
        const int cur = it & 1;
        const int nt  = t + GRID_MAIN;
        const bool hn = (nt < NTILES);

        if (hn) {
            const float* ap = emb + (size_t)(nt * 64 + arow) * HH + aseg * 4;
            #pragma unroll
            for (int j = 0; j < 8; j++) ra[j] = *(const float4*)(ap + j * 32);
            if (tid < 64) {
                int m = nt * 64 + tid;
                brow[(cur ^ 1) * 64 + tid] = batch[m];
                wrow[(cur ^ 1) * 64 + tid] =
                    (ntype[m] == 0) ? sgate[(it + 1) * 16 + (tid >> 2)] : 1.0f;
            }
        }

        float acc[8][4];
        #pragma unroll
        for (int ni = 0; ni < 8; ni++)
            #pragma unroll
            for (int r = 0; r < 4; r++) acc[ni][r] = 0.0f;

        const uint32_t ab = a_lm + (uint32_t)(cur * A_STAGE);
        #pragma unroll
        for (int ks = 0; ks < 16; ks++) {
            uint32_t af[4];
            LDMX4(af[0], af[1], af[2], af[3], ab + ks * 32);
            uint32_t bf[4][4];
            #pragma unroll
            for (int nip = 0; nip < 4; nip++)
                LDMX4(bf[nip][0], bf[nip][1], bf[nip][2], bf[nip][3],
                      b_lm + nip * 8448 + ks * 32);
            #pragma unroll
            for (int ni = 0; ni < 8; ni++)
                MMA16816(acc[ni][0], acc[ni][1], acc[ni][2], acc[ni][3],
                         af[0], af[1], af[2], af[3],
                         bf[ni >> 1][(ni & 1) * 2], bf[ni >> 1][(ni & 1) * 2 + 1]);
        }

        if (hn) {
            uint32_t base = sbase + A_OFF + (uint32_t)((cur ^ 1) * A_STAGE)
                          + (uint32_t)((arow * 264 + aseg * 4) * 2);
            #pragma unroll
            for (int j = 0; j < 8; j++) {
                __half2 h0 = __float22half2_rn(make_float2(ra[j].x, ra[j].y));
                __half2 h1 = __float22half2_rn(make_float2(ra[j].z, ra[j].w));
                asm volatile("st.shared.v2.b32 [%0], {%1,%2};"
                             :: "r"(base + j * 64),
                                "r"(*(uint32_t*)&h0), "r"(*(uint32_t*)&h1) : "memory");
            }
        }

        // ---- epilogue: bias + gate, shuffle segment-reduce, atomics ----
        {
            const int l1 = wm * 16 + (lane >> 2);
            const int l2 = l1 + 8;
            const int*   br = brow + cur * 64;
            const float* wr = wrow + cur * 64;
            const float w1 = wr[l1], w2 = wr[l2];
            #pragma unroll
            for (int ni = 0; ni < 8; ni++) {
                int c = wn * 64 + ni * 8 + (lane & 3) * 2;
                float b0 = sbias[c], b1 = sbias[c + 1];
                acc[ni][0] = (acc[ni][0] + b0) * w1;
                acc[ni][1] = (acc[ni][1] + b1) * w1;
                acc[ni][2] = (acc[ni][2] + b0) * w2;
                acc[ni][3] = (acc[ni][3] + b1) * w2;
            }
            const int glo = br[wm * 16], ghi = br[wm * 16 + 15];
            const int bg1 = br[l1], bg2 = br[l2];
            for (int g = glo; g <= ghi; g++) {
                const bool p1 = (bg1 == g), p2 = (bg2 == g);
                #pragma unroll
                for (int ni = 0; ni < 8; ni++) {
                    float s0 = (p1 ? acc[ni][0] : 0.0f) + (p2 ? acc[ni][2] : 0.0f);
                    float s1 = (p1 ? acc[ni][1] : 0.0f) + (p2 ? acc[ni][3] : 0.0f);
                    float m0v = fmaxf(p1 ? acc[ni][0] : -INFINITY, p2 ? acc[ni][2] : -INFINITY);
                    float m1v = fmaxf(p1 ? acc[ni][1] : -INFINITY, p2 ? acc[ni][3] : -INFINITY);
                    #pragma unroll
                    for (int off = 4; off < 32; off <<= 1) {
                        s0  += __shfl_xor_sync(0xffffffffu, s0,  off);
                        s1  += __shfl_xor_sync(0xffffffffu, s1,  off);
                        m0v = fmaxf(m0v, __shfl_xor_sync(0xffffffffu, m0v, off));
                        m1v = fmaxf(m1v, __shfl_xor_sync(0xffffffffu, m1v, off));
                    }
                    if (lane < 4) {
                        int c = wn * 64 + ni * 8 + lane * 2;
                        atomicAdd(&g_sums[g * HH + c],     s0);
                        atomicAdd(&g_sums[g * HH + c + 1], s1);
                        if (m0v > -INFINITY) atomicMaxF(&g_maxs[g * HH + c],     m0v);
                        if (m1v > -INFINITY) atomicMaxF(&g_maxs[g * HH + c + 1], m1v);
                    }
                }
            }
        }
        __syncthreads();
    }
}

// ---------------- final linear: 128 blocks x (4 graphs via thread split, 4 cols/thread) ----------------
__global__ __launch_bounds__(256) void final_kernel(
    const float* __restrict__ Wpost,
    const float* __restrict__ bpost,
    float* __restrict__ out)
{
    __shared__ float comb[4][516];     // row stride 516 floats (2064 B, 16B-aligned)
    __shared__ float invc[4];
    const int tid = threadIdx.x;
    const int g0  = blockIdx.x * 4;

    if (tid < 4) {
        int g = g0 + tid;
        invc[tid] = 1.0f / fmaxf((float)(g_start[g + 1] - g_start[g]), 1.0f);
    }
    __syncthreads();

    for (int idx = tid; idx < 4 * 512; idx += 256) {
        int g = idx >> 9;
        int k = idx & 511;
        float v;
        if (k < HH) {
            v = g_sums[(size_t)(g0 + g) * HH + k] * invc[g];
        } else {
            float m = g_maxs[(size_t)(g0 + g) * HH + (k - HH)];
            v = isfinite(m) ? m : 0.0f;
        }
        comb[g][k] = v;
    }
    __syncthreads();

    const int g  = tid >> 6;            // 0..3: graph within block
    const int c0 = (tid & 63) * 4;      // 4 consecutive output cols

    float4 acc = make_float4(0.0f, 0.0f, 0.0f, 0.0f);

    for (int k0 = 0; k0 < 2 * HH; k0 += 8) {
        float4 wv[8];
        #pragma unroll
        for (int u = 0; u < 8; u++)
            wv[u] = *(const float4*)&Wpost[(size_t)(k0 + u) * HH + c0];
        float4 cb0 = *(const float4*)&comb[g][k0];
        float4 cb1 = *(const float4*)&comb[g][k0 + 4];
        float cbs[8] = {cb0.x, cb0.y, cb0.z, cb0.w, cb1.x, cb1.y, cb1.z, cb1.w};
        #pragma unroll
        for (int u = 0; u < 8; u++) {
            acc.x = fmaf(cbs[u], wv[u].x, acc.x);
            acc.y = fmaf(cbs[u], wv[u].y, acc.y);
            acc.z = fmaf(cbs[u], wv[u].z, acc.z);
            acc.w = fmaf(cbs[u], wv[u].w, acc.w);
        }
    }

    float4 bb = *(const float4*)&bpost[c0];
    float4 res = make_float4(acc.x + bb.x, acc.y + bb.y, acc.z + bb.z, acc.w + bb.w);
    *(float4*)&out[(size_t)(g0 + g) * HH + c0] = res;
}

// ---------------- launch ----------------
extern "C" void kernel_launch(void* const* d_in, const int* in_sizes, int n_in,
                              void* d_out, int out_size)
{
    const float* emb   = (const float*)d_in[0];
    const int*   batch = (const int*)  d_in[1];
    const float* props = (const float*)d_in[2];
    const int*   ntype = (const int*)  d_in[3];
    const float* Wpre  = (const float*)d_in[4];
    const float* bpre  = (const float*)d_in[5];
    const float* W1    = (const float*)d_in[6];
    const float* b1    = (const float*)d_in[7];
    const float* W2    = (const float*)d_in[8];
    const float* b2    = (const float*)d_in[9];
    const float* Wpost = (const float*)d_in[10];
    const float* bpost = (const float*)d_in[11];
    float* out = (float*)d_out;

    cudaFuncSetAttribute(main_kernel, cudaFuncAttributeMaxDynamicSharedMemorySize, SMEM_SZ);

    void* p_sums = nullptr;
    void* p_maxs = nullptr;
    cudaGetSymbolAddress(&p_sums, g_sums);
    cudaGetSymbolAddress(&p_maxs, g_maxs);
    cudaMemsetAsync(p_sums, 0x00, NG * HH * sizeof(float));
    cudaMemsetAsync(p_maxs, 0xFF, NG * HH * sizeof(float));   // NaN -> acts as -inf for our atomics

    main_kernel<<<GRID_MAIN, 512, SMEM_SZ>>>(emb, batch, ntype, bpre, Wpre,
                                             props, W1, b1, W2, b2);
    final_kernel<<<NG / 4, 256>>>(Wpost, bpost, out);
}

// round 12
// speedup vs baseline: 1.2311x; 1.2147x over previous
#include <cuda_runtime.h>
#include <cuda_fp16.h>
#include <math.h>
#include <stdint.h>

#define NN   262144
#define HH   256
#define NV   65536
#define NG   512
#define NP   8
#define NHID 64

#define NTILES    4096      // NN / 64
#define GRID_MAIN 148

// ---------------- device globals ----------------
__device__ float  g_sums[NG * HH];
__device__ float  g_maxs[NG * HH];
__device__ int    g_start[NG + 1];

// ---------------- helpers ----------------
__device__ __forceinline__ uint32_t smem_u32(const void* p) {
    uint32_t a;
    asm("{ .reg .u64 t; cvta.to.shared.u64 t, %1; cvt.u32.u64 %0, t; }" : "=r"(a) : "l"(p));
    return a;
}
__device__ __forceinline__ void cp16(uint32_t dst, const void* src) {
    asm volatile("cp.async.cg.shared.global [%0], [%1], 16;" :: "r"(dst), "l"(src));
}
__device__ __forceinline__ void atomicMaxF(float* addr, float v) {
    if (v >= 0.0f) atomicMax((int*)addr, __float_as_int(v));
    else           atomicMin((unsigned int*)addr, __float_as_uint(v));
}
#define LDMX4(r0,r1,r2,r3,addr) \
    asm volatile("ldmatrix.sync.aligned.m8n8.x4.shared.b16 {%0,%1,%2,%3}, [%4];" \
                 : "=r"(r0), "=r"(r1), "=r"(r2), "=r"(r3) : "r"(addr))
#define MMA16816(c0,c1,c2,c3,a0,a1,a2,a3,b0,b1) \
    asm volatile("mma.sync.aligned.m16n8k16.row.col.f32.f16.f16.f32 " \
                 "{%0,%1,%2,%3}, {%4,%5,%6,%7}, {%8,%9}, {%0,%1,%2,%3};" \
                 : "+f"(c0), "+f"(c1), "+f"(c2), "+f"(c3) \
                 : "r"(a0), "r"(a1), "r"(a2), "r"(a3), "r"(b0), "r"(b1))

// ---------------- main: persistent HMMA GEMM; prep fully absorbed ----------------
// smem layout (206848 B dynamic):
//   B:        [0, 135168)                256 rows x 264 halfs (stride 528 B)
//   A stages: [135168, 135168+2*33792)   2 x (64 rows x 264 halfs)
//   misc at 202752:
//     brow[2][64] int (512) | wrow[2][64] f (512) | sbias[256] f (1024) | sgate[448] f (1792)
#define A_OFF    135168
#define A_STAGE  33792
#define MISC_OFF 202752
#define SMEM_SZ  206848

__global__ __launch_bounds__(512, 1) void main_kernel(
    const float* __restrict__ emb,
    const int*   __restrict__ batch,
    const int*   __restrict__ ntype,
    const float* __restrict__ bpre,
    const float* __restrict__ Wpre,
    const float* __restrict__ props,
    const float* __restrict__ W1, const float* __restrict__ b1,
    const float* __restrict__ W2, const float* __restrict__ b2)
{
    extern __shared__ char sm[];
    const uint32_t sbase = smem_u32(sm);
    int*   brow  = (int*)  (sm + MISC_OFF);            // [2][64]
    float* wrow  = (float*)(sm + MISC_OFF + 512);      // [2][64]
    float* sbias = (float*)(sm + MISC_OFF + 1024);     // [256]
    float* sgate = (float*)(sm + MISC_OFF + 2048);     // [448]

    const int tid  = threadIdx.x;
    const int wid  = tid >> 5;
    const int lane = tid & 31;
    const int wm   = wid >> 2;     // 0..3: rows [wm*16, +16)
    const int wn   = wid & 3;      // 0..3: cols [wn*64, +64)
    const int t0   = blockIdx.x;

    // ---- phase A: B transpose+convert, gates, g_start scan, sbias, A(t0) LDG ----

    // B: Wpre[k][n] -> Bs[n][k] fp16 (coalesced LDG.32 across n at fixed k)
    {
        const int bn  = tid & 255;       // output row n
        const int bk0 = (tid >> 8) * 128;
        const uint32_t bdst = sbase + (uint32_t)(bn * 528 + bk0 * 2);
        #pragma unroll
        for (int jj = 0; jj < 16; jj++) {
            float v[8];
            #pragma unroll
            for (int i = 0; i < 8; i++)
                v[i] = __ldg(&Wpre[(size_t)(bk0 + jj * 8 + i) * 256 + bn]);
            __half2 q0 = __float22half2_rn(make_float2(v[0], v[1]));
            __half2 q1 = __float22half2_rn(make_float2(v[2], v[3]));
            __half2 q2 = __float22half2_rn(make_float2(v[4], v[5]));
            __half2 q3 = __float22half2_rn(make_float2(v[6], v[7]));
            asm volatile("st.shared.v4.b32 [%0], {%1,%2,%3,%4};"
                         :: "r"(bdst + jj * 16),
                            "r"(*(uint32_t*)&q0), "r"(*(uint32_t*)&q1),
                            "r"(*(uint32_t*)&q2), "r"(*(uint32_t*)&q3) : "memory");
        }
    }

    // gates for this CTA's tiles only
    {
        const int nt_cta = (NTILES - 1 - t0) / GRID_MAIN + 1;   // 27 or 28
        if (tid < nt_cta * 16) {
            const int j = tid >> 4, r = tid & 15;
            const int var = (t0 + j * GRID_MAIN) * 16 + r;
            float4 p0 = __ldg((const float4*)props + var * 2);
            float4 p1 = __ldg((const float4*)props + var * 2 + 1);
            float pr[NP] = {p0.x, p0.y, p0.z, p0.w, p1.x, p1.y, p1.z, p1.w};
            float accA = __ldg(b2), accB = 0.0f;
            #pragma unroll
            for (int jh = 0; jh < NHID; jh += 4) {
                float s0 = __ldg(b1 + jh),     s1 = __ldg(b1 + jh + 1);
                float s2 = __ldg(b1 + jh + 2), s3 = __ldg(b1 + jh + 3);
                #pragma unroll
                for (int p = 0; p < NP; p++) {
                    float pv = pr[p];
                    const float* w = W1 + p * NHID + jh;
                    s0 = fmaf(pv, __ldg(w),     s0);
                    s1 = fmaf(pv, __ldg(w + 1), s1);
                    s2 = fmaf(pv, __ldg(w + 2), s2);
                    s3 = fmaf(pv, __ldg(w + 3), s3);
                }
                accA = fmaf(fmaxf(s0, 0.0f), __ldg(W2 + jh),     accA);
                accB = fmaf(fmaxf(s1, 0.0f), __ldg(W2 + jh + 1), accB);
                accA = fmaf(fmaxf(s2, 0.0f), __ldg(W2 + jh + 2), accA);
                accB = fmaf(fmaxf(s3, 0.0f), __ldg(W2 + jh + 3), accB);
            }
            sgate[tid] = 1.0f / (1.0f + expf(-(accA + accB)));
        }
    }

    // segment boundary scan (first 65536 global threads, 4 nodes each)
    {
        int gid = t0 * 512 + tid;
        if (gid < NN / 4) {
            int i0 = gid * 4;
            int4 b4 = *(const int4*)&batch[i0];
            int v[4] = {b4.x, b4.y, b4.z, b4.w};
            int p = (i0 == 0) ? -1 : __ldg(&batch[i0 - 1]);
            #pragma unroll
            for (int e = 0; e < 4; e++) {
                for (int g = p + 1; g <= v[e]; g++) g_start[g] = i0 + e;
                p = v[e];
            }
            if (i0 + 4 == NN)
                for (int g = v[3] + 1; g <= NG; g++) g_start[g] = NN;
        }
    }

    if (tid < 256) sbias[tid] = bpre[tid];

    const int arow = tid >> 3;     // 0..63
    const int aseg = tid & 7;      // float4 slot
    const uint32_t a_sts0 = sbase + A_OFF + (uint32_t)((arow * 264 + aseg * 4) * 2);

    float4 ra[8];
    {
        const float* ap = emb + (size_t)(t0 * 64 + arow) * HH + aseg * 4;
        #pragma unroll
        for (int j = 0; j < 8; j++) ra[j] = *(const float4*)(ap + j * 32);
    }
    __syncthreads();

    // ---- phase B: A(t0) STS, brow/wrow(t0) (needs sgate) ----
    {
        #pragma unroll
        for (int j = 0; j < 8; j++) {
            __half2 h0 = __float22half2_rn(make_float2(ra[j].x, ra[j].y));
            __half2 h1 = __float22half2_rn(make_float2(ra[j].z, ra[j].w));
            asm volatile("st.shared.v2.b32 [%0], {%1,%2};"
                         :: "r"(a_sts0 + j * 64),
                            "r"(*(uint32_t*)&h0), "r"(*(uint32_t*)&h1) : "memory");
        }
    }
    if (tid < 64) {
        int m = t0 * 64 + tid;
        brow[tid] = batch[m];
        wrow[tid] = (ntype[m] == 0) ? sgate[tid >> 2] : 1.0f;
    }
    __syncthreads();

    // ldmatrix lane addresses (stride 264 halfs -> conflict-free)
    const uint32_t a_lm = sbase + A_OFF +
        (uint32_t)(((wm * 16 + (lane & 15)) * 264 + (lane >> 4) * 8) * 2);
    const uint32_t b_lm = sbase +
        (uint32_t)(((wn * 64 + (lane >> 4) * 8 + (lane & 7)) * 264 + ((lane >> 3) & 1) * 8) * 2);

    for (int t = t0, it = 0; t < NTILES; t += GRID_MAIN, it++) {
        const int cur = it & 1;
        const int nt  = t + GRID_MAIN;
        const bool hn = (nt < NTILES);

        if (hn) {
            const float* ap = emb + (size_t)(nt * 64 + arow) * HH + aseg * 4;
            #pragma unroll
            for (int j = 0; j < 8; j++) ra[j] = *(const float4*)(ap + j * 32);
            if (tid < 64) {
                int m = nt * 64 + tid;
                brow[(cur ^ 1) * 64 + tid] = batch[m];
                wrow[(cur ^ 1) * 64 + tid] =
                    (ntype[m] == 0) ? sgate[(it + 1) * 16 + (tid >> 2)] : 1.0f;
            }
        }

        float acc[8][4];
        #pragma unroll
        for (int ni = 0; ni < 8; ni++)
            #pragma unroll
            for (int r = 0; r < 4; r++) acc[ni][r] = 0.0f;

        const uint32_t ab = a_lm + (uint32_t)(cur * A_STAGE);
        #pragma unroll
        for (int ks = 0; ks < 16; ks++) {
            uint32_t af[4];
            LDMX4(af[0], af[1], af[2], af[3], ab + ks * 32);
            uint32_t bf[4][4];
            #pragma unroll
            for (int nip = 0; nip < 4; nip++)
                LDMX4(bf[nip][0], bf[nip][1], bf[nip][2], bf[nip][3],
                      b_lm + nip * 8448 + ks * 32);
            #pragma unroll
            for (int ni = 0; ni < 8; ni++)
                MMA16816(acc[ni][0], acc[ni][1], acc[ni][2], acc[ni][3],
                         af[0], af[1], af[2], af[3],
                         bf[ni >> 1][(ni & 1) * 2], bf[ni >> 1][(ni & 1) * 2 + 1]);
        }

        if (hn) {
            uint32_t base = sbase + A_OFF + (uint32_t)((cur ^ 1) * A_STAGE)
                          + (uint32_t)((arow * 264 + aseg * 4) * 2);
            #pragma unroll
            for (int j = 0; j < 8; j++) {
                __half2 h0 = __float22half2_rn(make_float2(ra[j].x, ra[j].y));
                __half2 h1 = __float22half2_rn(make_float2(ra[j].z, ra[j].w));
                asm volatile("st.shared.v2.b32 [%0], {%1,%2};"
                             :: "r"(base + j * 64),
                                "r"(*(uint32_t*)&h0), "r"(*(uint32_t*)&h1) : "memory");
            }
        }

        // ---- epilogue: bias + gate, shuffle segment-reduce, atomics ----
        {
            const int l1 = wm * 16 + (lane >> 2);
            const int l2 = l1 + 8;
            const int*   br = brow + cur * 64;
            const float* wr = wrow + cur * 64;
            const float w1 = wr[l1], w2 = wr[l2];
            #pragma unroll
            for (int ni = 0; ni < 8; ni++) {
                int c = wn * 64 + ni * 8 + (lane & 3) * 2;
                float b0 = sbias[c], b1 = sbias[c + 1];
                acc[ni][0] = (acc[ni][0] + b0) * w1;
                acc[ni][1] = (acc[ni][1] + b1) * w1;
                acc[ni][2] = (acc[ni][2] + b0) * w2;
                acc[ni][3] = (acc[ni][3] + b1) * w2;
            }
            const int glo = br[wm * 16], ghi = br[wm * 16 + 15];
            const int bg1 = br[l1], bg2 = br[l2];
            for (int g = glo; g <= ghi; g++) {
                const bool p1 = (bg1 == g), p2 = (bg2 == g);
                #pragma unroll
                for (int ni = 0; ni < 8; ni++) {
                    float s0 = (p1 ? acc[ni][0] : 0.0f) + (p2 ? acc[ni][2] : 0.0f);
                    float s1 = (p1 ? acc[ni][1] : 0.0f) + (p2 ? acc[ni][3] : 0.0f);
                    float m0v = fmaxf(p1 ? acc[ni][0] : -INFINITY, p2 ? acc[ni][2] : -INFINITY);
                    float m1v = fmaxf(p1 ? acc[ni][1] : -INFINITY, p2 ? acc[ni][3] : -INFINITY);
                    #pragma unroll
                    for (int off = 4; off < 32; off <<= 1) {
                        s0  += __shfl_xor_sync(0xffffffffu, s0,  off);
                        s1  += __shfl_xor_sync(0xffffffffu, s1,  off);
                        m0v = fmaxf(m0v, __shfl_xor_sync(0xffffffffu, m0v, off));
                        m1v = fmaxf(m1v, __shfl_xor_sync(0xffffffffu, m1v, off));
                    }
                    if (lane < 4) {
                        int c = wn * 64 + ni * 8 + lane * 2;
                        atomicAdd(&g_sums[g * HH + c],     s0);
                        atomicAdd(&g_sums[g * HH + c + 1], s1);
                        if (m0v > -INFINITY) atomicMaxF(&g_maxs[g * HH + c],     m0v);
                        if (m1v > -INFINITY) atomicMaxF(&g_maxs[g * HH + c + 1], m1v);
                    }
                }
            }
        }
        __syncthreads();
    }
}

// ---------------- final linear: cooperative cp.async staging of Wpost ----------------
// dyn smem: sw 2 x (32 x 256 f) = 65536 | comb 4x512 f = 8192 | invc 16  -> 73744 B
#define FK_SMEM 73744

__global__ __launch_bounds__(256) void final_kernel(
    const float* __restrict__ Wpost,
    const float* __restrict__ bpost,
    float* __restrict__ out)
{
    extern __shared__ char fsm[];
    float* swf   = (float*)fsm;                 // [2][32][256]
    float* comb  = (float*)(fsm + 65536);       // [4][512]
    float* invc  = (float*)(fsm + 73728);       // [4]
    const uint32_t sbase = smem_u32(fsm);

    const int tid = threadIdx.x;
    const int g0  = blockIdx.x * 4;

    if (tid < 4) {
        int g = g0 + tid;
        invc[tid] = 1.0f / fmaxf((float)(g_start[g + 1] - g_start[g]), 1.0f);
    }

    // prologue: issue k-tiles 0 and 1 (each 32x256 f = 2048 x 16B, 8 per thread)
    #pragma unroll
    for (int i = 0; i < 8; i++) {
        int u = tid + i * 256;
        cp16(sbase + (uint32_t)((u >> 6) * 1024 + (u & 63) * 16),
             Wpost + (size_t)(u >> 6) * 256 + (u & 63) * 4);
    }
    asm volatile("cp.async.commit_group;" ::: "memory");
    #pragma unroll
    for (int i = 0; i < 8; i++) {
        int u = tid + i * 256;
        cp16(sbase + 32768u + (uint32_t)((u >> 6) * 1024 + (u & 63) * 16),
             Wpost + (size_t)(32 + (u >> 6)) * 256 + (u & 63) * 4);
    }
    asm volatile("cp.async.commit_group;" ::: "memory");

    // fill comb (overlaps with cp.async)
    for (int idx = tid; idx < 4 * 512; idx += 256) {
        int g = idx >> 9;
        int k = idx & 511;
        float v;
        if (k < HH) {
            v = g_sums[(size_t)(g0 + g) * HH + k];   // scaled below by invc after sync
        } else {
            float m = g_maxs[(size_t)(g0 + g) * HH + (k - HH)];
            v = isfinite(m) ? m : 0.0f;
        }
        comb[idx] = v;
    }
    __syncthreads();
    // scale mean part by invc (needs invc visible)
    for (int idx = tid; idx < 4 * 512; idx += 256) {
        int g = idx >> 9;
        int k = idx & 511;
        if (k < HH) comb[idx] *= invc[g];
    }

    const int g  = tid >> 6;            // 0..3
    const int c0 = (tid & 63) * 4;      // 4 consecutive cols
    float4 acc = make_float4(0.0f, 0.0f, 0.0f, 0.0f);

    for (int t = 0; t < 16; t++) {
        if (t < 15) { asm volatile("cp.async.wait_group 1;" ::: "memory"); }
        else        { asm volatile("cp.async.wait_group 0;" ::: "memory"); }
        __syncthreads();   // tile t visible to all; comb scaling also synced on t=0

        const float* wb = swf + (t & 1) * 8192;
        float4 cb[8];
        #pragma unroll
        for (int u = 0; u < 8; u++)
            cb[u] = *(const float4*)&comb[g * 512 + t * 32 + u * 4];
        const float* cbs = (const float*)cb;
        #pragma unroll
        for (int k = 0; k < 32; k++) {
            float cv = cbs[k];
            float4 w = *(const float4*)&wb[k * 256 + c0];
            acc.x = fmaf(cv, w.x, acc.x);
            acc.y = fmaf(cv, w.y, acc.y);
            acc.z = fmaf(cv, w.z, acc.z);
            acc.w = fmaf(cv, w.w, acc.w);
        }
        __syncthreads();   // all threads done with buffer (t&1)

        if (t + 2 < 16) {
            uint32_t dst = sbase + (uint32_t)((t & 1) * 32768);
            const float* src = Wpost + (size_t)(t + 2) * 32 * 256;
            #pragma unroll
            for (int i = 0; i < 8; i++) {
                int u = tid + i * 256;
                cp16(dst + (uint32_t)((u >> 6) * 1024 + (u & 63) * 16),
                     src + (size_t)(u >> 6) * 256 + (u & 63) * 4);
            }
            asm volatile("cp.async.commit_group;" ::: "memory");
        }
    }

    float4 bb = *(const float4*)&bpost[c0];
    float4 res = make_float4(acc.x + bb.x, acc.y + bb.y, acc.z + bb.z, acc.w + bb.w);
    *(float4*)&out[(size_t)(g0 + g) * HH + c0] = res;
}

// ---------------- launch ----------------
extern "C" void kernel_launch(void* const* d_in, const int* in_sizes, int n_in,
                              void* d_out, int out_size)
{
    const float* emb   = (const float*)d_in[0];
    const int*   batch = (const int*)  d_in[1];
    const float* props = (const float*)d_in[2];
    const int*   ntype = (const int*)  d_in[3];
    const float* Wpre  = (const float*)d_in[4];
    const float* bpre  = (const float*)d_in[5];
    const float* W1    = (const float*)d_in[6];
    const float* b1    = (const float*)d_in[7];
    const float* W2    = (const float*)d_in[8];
    const float* b2    = (const float*)d_in[9];
    const float* Wpost = (const float*)d_in[10];
    const float* bpost = (const float*)d_in[11];
    float* out = (float*)d_out;

    cudaFuncSetAttribute(main_kernel, cudaFuncAttributeMaxDynamicSharedMemorySize, SMEM_SZ);
    cudaFuncSetAttribute(final_kernel, cudaFuncAttributeMaxDynamicSharedMemorySize, FK_SMEM);

    void* p_sums = nullptr;
    void* p_maxs = nullptr;
    cudaGetSymbolAddress(&p_sums, g_sums);
    cudaGetSymbolAddress(&p_maxs, g_maxs);
    cudaMemsetAsync(p_sums, 0x00, NG * HH * sizeof(float));
    cudaMemsetAsync(p_maxs, 0xFF, NG * HH * sizeof(float));   // NaN -> acts as -inf for our atomics

    main_kernel<<<GRID_MAIN, 512, SMEM_SZ>>>(emb, batch, ntype, bpre, Wpre,
                                             props, W1, b1, W2, b2);
    final_kernel<<<NG / 4, 256, FK_SMEM>>>(Wpost, bpost, out);
}

// round 13
// speedup vs baseline: 1.3999x; 1.1371x over previous
#include <cuda_runtime.h>
#include <cuda_fp16.h>
#include <math.h>
#include <stdint.h>

#define NN   262144
#define HH   256
#define NV   65536
#define NG   512
#define NP   8
#define NHID 64

#define NTILES    4096      // NN / 64
#define GRID_MAIN 148

// ---------------- device globals ----------------
__device__ float  g_sums[NG * HH];
__device__ float  g_maxs[NG * HH];
__device__ int    g_start[NG + 1];

// ---------------- helpers ----------------
__device__ __forceinline__ uint32_t smem_u32(const void* p) {
    uint32_t a;
    asm("{ .reg .u64 t; cvta.to.shared.u64 t, %1; cvt.u32.u64 %0, t; }" : "=r"(a) : "l"(p));
    return a;
}
__device__ __forceinline__ void cp16(uint32_t dst, const void* src) {
    asm volatile("cp.async.cg.shared.global [%0], [%1], 16;" :: "r"(dst), "l"(src));
}
__device__ __forceinline__ void atomicMaxF(float* addr, float v) {
    if (v >= 0.0f) atomicMax((int*)addr, __float_as_int(v));
    else           atomicMin((unsigned int*)addr, __float_as_uint(v));
}
#define LDMX4(r0,r1,r2,r3,addr) \
    asm volatile("ldmatrix.sync.aligned.m8n8.x4.shared.b16 {%0,%1,%2,%3}, [%4];" \
                 : "=r"(r0), "=r"(r1), "=r"(r2), "=r"(r3) : "r"(addr))
#define MMA16816(c0,c1,c2,c3,a0,a1,a2,a3,b0,b1) \
    asm volatile("mma.sync.aligned.m16n8k16.row.col.f32.f16.f16.f32 " \
                 "{%0,%1,%2,%3}, {%4,%5,%6,%7}, {%8,%9}, {%0,%1,%2,%3};" \
                 : "+f"(c0), "+f"(c1), "+f"(c2), "+f"(c3) \
                 : "r"(a0), "r"(a1), "r"(a2), "r"(a3), "r"(b0), "r"(b1))

// ---------------- main: persistent HMMA GEMM; contiguous tiles; carry epilogue ----------------
// smem layout (206848 B dynamic):
//   B:        [0, 135168)                256 rows x 264 halfs (stride 528 B)
//   A stages: [135168, 135168+2*33792)   2 x (64 rows x 264 halfs)
//   misc at 202752:
//     brow[2][64] int (512) | wrow[2][64] f (512) | sbias[256] f (1024) | sgate[448] f (1792)
#define A_OFF    135168
#define A_STAGE  33792
#define MISC_OFF 202752
#define SMEM_SZ  206848

__global__ __launch_bounds__(512, 1) void main_kernel(
    const float* __restrict__ emb,
    const int*   __restrict__ batch,
    const int*   __restrict__ ntype,
    const float* __restrict__ bpre,
    const float* __restrict__ Wpre,
    const float* __restrict__ props,
    const float* __restrict__ W1, const float* __restrict__ b1,
    const float* __restrict__ W2, const float* __restrict__ b2)
{
    extern __shared__ char sm[];
    const uint32_t sbase = smem_u32(sm);
    int*   brow  = (int*)  (sm + MISC_OFF);            // [2][64]
    float* wrow  = (float*)(sm + MISC_OFF + 512);      // [2][64]
    float* sbias = (float*)(sm + MISC_OFF + 1024);     // [256]
    float* sgate = (float*)(sm + MISC_OFF + 2048);     // [448]

    const int tid  = threadIdx.x;
    const int wid  = tid >> 5;
    const int lane = tid & 31;
    const int wm   = wid >> 2;     // 0..3: rows [wm*16, +16)
    const int wn   = wid & 3;      // 0..3: cols [wn*64, +64)
    const int b    = blockIdx.x;

    // contiguous tile range: blocks 0..99 get 28 tiles, 100..147 get 27
    const int tstart = b * 27 + min(b, 100);
    const int tcnt   = 27 + (b < 100 ? 1 : 0);

    // ---- phase A: B transpose+convert, gates, g_start scan, sbias, A(tstart) LDG ----

    // B: Wpre[k][n] -> Bs[n][k] fp16 (coalesced LDG.32 across n at fixed k)
    {
        const int bn  = tid & 255;       // output row n
        const int bk0 = (tid >> 8) * 128;
        const uint32_t bdst = sbase + (uint32_t)(bn * 528 + bk0 * 2);
        #pragma unroll
        for (int jj = 0; jj < 16; jj++) {
            float v[8];
            #pragma unroll
            for (int i = 0; i < 8; i++)
                v[i] = __ldg(&Wpre[(size_t)(bk0 + jj * 8 + i) * 256 + bn]);
            __half2 q0 = __float22half2_rn(make_float2(v[0], v[1]));
            __half2 q1 = __float22half2_rn(make_float2(v[2], v[3]));
            __half2 q2 = __float22half2_rn(make_float2(v[4], v[5]));
            __half2 q3 = __float22half2_rn(make_float2(v[6], v[7]));
            asm volatile("st.shared.v4.b32 [%0], {%1,%2,%3,%4};"
                         :: "r"(bdst + jj * 16),
                            "r"(*(uint32_t*)&q0), "r"(*(uint32_t*)&q1),
                            "r"(*(uint32_t*)&q2), "r"(*(uint32_t*)&q3) : "memory");
        }
    }

    // gates for this CTA's contiguous var range [tstart*16, (tstart+tcnt)*16)
    {
        if (tid < tcnt * 16) {
            const int var = tstart * 16 + tid;
            float4 p0 = __ldg((const float4*)props + var * 2);
            float4 p1 = __ldg((const float4*)props + var * 2 + 1);
            float pr[NP] = {p0.x, p0.y, p0.z, p0.w, p1.x, p1.y, p1.z, p1.w};
            float accA = __ldg(b2), accB = 0.0f;
            #pragma unroll
            for (int jh = 0; jh < NHID; jh += 4) {
                float s0 = __ldg(b1 + jh),     s1 = __ldg(b1 + jh + 1);
                float s2 = __ldg(b1 + jh + 2), s3 = __ldg(b1 + jh + 3);
                #pragma unroll
                for (int p = 0; p < NP; p++) {
                    float pv = pr[p];
                    const float* w = W1 + p * NHID + jh;
                    s0 = fmaf(pv, __ldg(w),     s0);
                    s1 = fmaf(pv, __ldg(w + 1), s1);
                    s2 = fmaf(pv, __ldg(w + 2), s2);
                    s3 = fmaf(pv, __ldg(w + 3), s3);
                }
                accA = fmaf(fmaxf(s0, 0.0f), __ldg(W2 + jh),     accA);
                accB = fmaf(fmaxf(s1, 0.0f), __ldg(W2 + jh + 1), accB);
                accA = fmaf(fmaxf(s2, 0.0f), __ldg(W2 + jh + 2), accA);
                accB = fmaf(fmaxf(s3, 0.0f), __ldg(W2 + jh + 3), accB);
            }
            sgate[tid] = 1.0f / (1.0f + expf(-(accA + accB)));
        }
    }

    // segment boundary scan (first 65536 global threads, 4 nodes each)
    {
        int gid = b * 512 + tid;
        if (gid < NN / 4) {
            int i0 = gid * 4;
            int4 b4 = *(const int4*)&batch[i0];
            int v[4] = {b4.x, b4.y, b4.z, b4.w};
            int p = (i0 == 0) ? -1 : __ldg(&batch[i0 - 1]);
            #pragma unroll
            for (int e = 0; e < 4; e++) {
                for (int g = p + 1; g <= v[e]; g++) g_start[g] = i0 + e;
                p = v[e];
            }
            if (i0 + 4 == NN)
                for (int g = v[3] + 1; g <= NG; g++) g_start[g] = NN;
        }
    }

    if (tid < 256) sbias[tid] = bpre[tid];

    const int arow = tid >> 3;     // 0..63
    const int aseg = tid & 7;      // float4 slot
    const uint32_t a_sts0 = sbase + A_OFF + (uint32_t)((arow * 264 + aseg * 4) * 2);

    // A prefetch held as half2 (16 regs)
    uint32_t rh[16];
    {
        const float* ap = emb + (size_t)(tstart * 64 + arow) * HH + aseg * 4;
        #pragma unroll
        for (int j = 0; j < 8; j++) {
            float4 a = *(const float4*)(ap + j * 32);
            __half2 h0 = __float22half2_rn(make_float2(a.x, a.y));
            __half2 h1 = __float22half2_rn(make_float2(a.z, a.w));
            rh[2 * j]     = *(uint32_t*)&h0;
            rh[2 * j + 1] = *(uint32_t*)&h1;
        }
    }
    __syncthreads();

    // ---- phase B: A(tstart) STS, brow/wrow(tstart) ----
    #pragma unroll
    for (int j = 0; j < 8; j++) {
        asm volatile("st.shared.v2.b32 [%0], {%1,%2};"
                     :: "r"(a_sts0 + j * 64), "r"(rh[2 * j]), "r"(rh[2 * j + 1]) : "memory");
    }
    if (tid < 64) {
        int m = tstart * 64 + tid;
        brow[tid] = batch[m];
        wrow[tid] = (ntype[m] == 0) ? sgate[tid >> 2] : 1.0f;
    }
    __syncthreads();

    // ldmatrix lane addresses (stride 264 halfs -> conflict-free)
    const uint32_t a_lm = sbase + A_OFF +
        (uint32_t)(((wm * 16 + (lane & 15)) * 264 + (lane >> 4) * 8) * 2);
    const uint32_t b_lm = sbase +
        (uint32_t)(((wn * 64 + (lane >> 4) * 8 + (lane & 7)) * 264 + ((lane >> 3) & 1) * 8) * 2);

    // carry state
    int   carry_g = -1;
    float cs[8][2], cm[8][2];

    auto flush_carry = [&]() {
        #pragma unroll
        for (int ni = 0; ni < 8; ni++) {
            float s0 = cs[ni][0], s1 = cs[ni][1];
            float m0 = cm[ni][0], m1 = cm[ni][1];
            #pragma unroll
            for (int off = 4; off < 32; off <<= 1) {
                s0 += __shfl_xor_sync(0xffffffffu, s0, off);
                s1 += __shfl_xor_sync(0xffffffffu, s1, off);
                m0 = fmaxf(m0, __shfl_xor_sync(0xffffffffu, m0, off));
                m1 = fmaxf(m1, __shfl_xor_sync(0xffffffffu, m1, off));
            }
            if (lane < 4) {
                int c = wn * 64 + ni * 8 + lane * 2;
                atomicAdd(&g_sums[carry_g * HH + c],     s0);
                atomicAdd(&g_sums[carry_g * HH + c + 1], s1);
                atomicMaxF(&g_maxs[carry_g * HH + c],     m0);
                atomicMaxF(&g_maxs[carry_g * HH + c + 1], m1);
            }
        }
    };

    for (int it = 0; it < tcnt; it++) {
        const int cur = it & 1;
        const bool hn = (it + 1 < tcnt);
        const int nt  = tstart + it + 1;

        if (hn) {
            const float* ap = emb + (size_t)(nt * 64 + arow) * HH + aseg * 4;
            #pragma unroll
            for (int j = 0; j < 8; j++) {
                float4 a = *(const float4*)(ap + j * 32);
                __half2 h0 = __float22half2_rn(make_float2(a.x, a.y));
                __half2 h1 = __float22half2_rn(make_float2(a.z, a.w));
                rh[2 * j]     = *(uint32_t*)&h0;
                rh[2 * j + 1] = *(uint32_t*)&h1;
            }
            if (tid < 64) {
                int m = nt * 64 + tid;
                brow[(cur ^ 1) * 64 + tid] = batch[m];
                wrow[(cur ^ 1) * 64 + tid] =
                    (ntype[m] == 0) ? sgate[(it + 1) * 16 + (tid >> 2)] : 1.0f;
            }
        }

        float acc[8][4];
        #pragma unroll
        for (int ni = 0; ni < 8; ni++)
            #pragma unroll
            for (int r = 0; r < 4; r++) acc[ni][r] = 0.0f;

        const uint32_t ab = a_lm + (uint32_t)(cur * A_STAGE);
        #pragma unroll
        for (int ks = 0; ks < 16; ks++) {
            uint32_t af[4];
            LDMX4(af[0], af[1], af[2], af[3], ab + ks * 32);
            uint32_t bf[4][4];
            #pragma unroll
            for (int nip = 0; nip < 4; nip++)
                LDMX4(bf[nip][0], bf[nip][1], bf[nip][2], bf[nip][3],
                      b_lm + nip * 8448 + ks * 32);
            #pragma unroll
            for (int ni = 0; ni < 8; ni++)
                MMA16816(acc[ni][0], acc[ni][1], acc[ni][2], acc[ni][3],
                         af[0], af[1], af[2], af[3],
                         bf[ni >> 1][(ni & 1) * 2], bf[ni >> 1][(ni & 1) * 2 + 1]);
        }

        if (hn) {
            uint32_t base = sbase + A_OFF + (uint32_t)((cur ^ 1) * A_STAGE)
                          + (uint32_t)((arow * 264 + aseg * 4) * 2);
            #pragma unroll
            for (int j = 0; j < 8; j++) {
                asm volatile("st.shared.v2.b32 [%0], {%1,%2};"
                             :: "r"(base + j * 64), "r"(rh[2 * j]), "r"(rh[2 * j + 1]) : "memory");
            }
        }

        // ---- epilogue: bias + gate, carry-based segment reduce ----
        {
            const int l1 = wm * 16 + (lane >> 2);
            const int l2 = l1 + 8;
            const int*   br = brow + cur * 64;
            const float* wr = wrow + cur * 64;
            const float w1 = wr[l1], w2 = wr[l2];
            #pragma unroll
            for (int ni = 0; ni < 8; ni++) {
                int c = wn * 64 + ni * 8 + (lane & 3) * 2;
                float b0 = sbias[c], b1 = sbias[c + 1];
                acc[ni][0] = (acc[ni][0] + b0) * w1;
                acc[ni][1] = (acc[ni][1] + b1) * w1;
                acc[ni][2] = (acc[ni][2] + b0) * w2;
                acc[ni][3] = (acc[ni][3] + b1) * w2;
            }
            const int gtop = br[wm * 16];
            const int gbot = br[wm * 16 + 15];
            if (gtop == gbot) {
                if (gtop == carry_g) {
                    #pragma unroll
                    for (int ni = 0; ni < 8; ni++) {
                        cs[ni][0] += acc[ni][0] + acc[ni][2];
                        cs[ni][1] += acc[ni][1] + acc[ni][3];
                        cm[ni][0] = fmaxf(cm[ni][0], fmaxf(acc[ni][0], acc[ni][2]));
                        cm[ni][1] = fmaxf(cm[ni][1], fmaxf(acc[ni][1], acc[ni][3]));
                    }
                } else {
                    if (carry_g >= 0) flush_carry();
                    carry_g = gtop;
                    #pragma unroll
                    for (int ni = 0; ni < 8; ni++) {
                        cs[ni][0] = acc[ni][0] + acc[ni][2];
                        cs[ni][1] = acc[ni][1] + acc[ni][3];
                        cm[ni][0] = fmaxf(acc[ni][0], acc[ni][2]);
                        cm[ni][1] = fmaxf(acc[ni][1], acc[ni][3]);
                    }
                }
            } else {
                if (carry_g >= 0) flush_carry();
                carry_g = -1;
                // slow path: boundary inside slice (~3% of tiles)
                const int bg1 = br[l1], bg2 = br[l2];
                for (int g = gtop; g <= gbot; g++) {
                    const bool p1 = (bg1 == g), p2 = (bg2 == g);
                    #pragma unroll
                    for (int ni = 0; ni < 8; ni++) {
                        float s0 = (p1 ? acc[ni][0] : 0.0f) + (p2 ? acc[ni][2] : 0.0f);
                        float s1 = (p1 ? acc[ni][1] : 0.0f) + (p2 ? acc[ni][3] : 0.0f);
                        float m0v = fmaxf(p1 ? acc[ni][0] : -INFINITY, p2 ? acc[ni][2] : -INFINITY);
                        float m1v = fmaxf(p1 ? acc[ni][1] : -INFINITY, p2 ? acc[ni][3] : -INFINITY);
                        #pragma unroll
                        for (int off = 4; off < 32; off <<= 1) {
                            s0  += __shfl_xor_sync(0xffffffffu, s0,  off);
                            s1  += __shfl_xor_sync(0xffffffffu, s1,  off);
                            m0v = fmaxf(m0v, __shfl_xor_sync(0xffffffffu, m0v, off));
                            m1v = fmaxf(m1v, __shfl_xor_sync(0xffffffffu, m1v, off));
                        }
                        if (lane < 4) {
                            int c = wn * 64 + ni * 8 + lane * 2;
                            atomicAdd(&g_sums[g * HH + c],     s0);
                            atomicAdd(&g_sums[g * HH + c + 1], s1);
                            if (m0v > -INFINITY) atomicMaxF(&g_maxs[g * HH + c],     m0v);
                            if (m1v > -INFINITY) atomicMaxF(&g_maxs[g * HH + c + 1], m1v);
                        }
                    }
                }
            }
        }
        __syncthreads();
    }

    if (carry_g >= 0) flush_carry();
}

// ---------------- final linear: cooperative cp.async staging of Wpost ----------------
// dyn smem: sw 2 x (32 x 256 f) = 65536 | comb 4x512 f = 8192 | invc 16  -> 73744 B
#define FK_SMEM 73744

__global__ __launch_bounds__(256) void final_kernel(
    const float* __restrict__ Wpost,
    const float* __restrict__ bpost,
    float* __restrict__ out)
{
    extern __shared__ char fsm[];
    float* swf   = (float*)fsm;                 // [2][32][256]
    float* comb  = (float*)(fsm + 65536);       // [4][512]
    float* invc  = (float*)(fsm + 73728);       // [4]
    const uint32_t sbase = smem_u32(fsm);

    const int tid = threadIdx.x;
    const int g0  = blockIdx.x * 4;

    if (tid < 4) {
        int g = g0 + tid;
        invc[tid] = 1.0f / fmaxf((float)(g_start[g + 1] - g_start[g]), 1.0f);
    }

    #pragma unroll
    for (int i = 0; i < 8; i++) {
        int u = tid + i * 256;
        cp16(sbase + (uint32_t)((u >> 6) * 1024 + (u & 63) * 16),
             Wpost + (size_t)(u >> 6) * 256 + (u & 63) * 4);
    }
    asm volatile("cp.async.commit_group;" ::: "memory");
    #pragma unroll
    for (int i = 0; i < 8; i++) {
        int u = tid + i * 256;
        cp16(sbase + 32768u + (uint32_t)((u >> 6) * 1024 + (u & 63) * 16),
             Wpost + (size_t)(32 + (u >> 6)) * 256 + (u & 63) * 4);
    }
    asm volatile("cp.async.commit_group;" ::: "memory");

    for (int idx = tid; idx < 4 * 512; idx += 256) {
        int g = idx >> 9;
        int k = idx & 511;
        float v;
        if (k < HH) {
            v = g_sums[(size_t)(g0 + g) * HH + k];
        } else {
            float m = g_maxs[(size_t)(g0 + g) * HH + (k - HH)];
            v = isfinite(m) ? m : 0.0f;
        }
        comb[idx] = v;
    }
    __syncthreads();
    for (int idx = tid; idx < 4 * 512; idx += 256) {
        int g = idx >> 9;
        int k = idx & 511;
        if (k < HH) comb[idx] *= invc[g];
    }

    const int g  = tid >> 6;
    const int c0 = (tid & 63) * 4;
    float4 acc = make_float4(0.0f, 0.0f, 0.0f, 0.0f);

    for (int t = 0; t < 16; t++) {
        if (t < 15) { asm volatile("cp.async.wait_group 1;" ::: "memory"); }
        else        { asm volatile("cp.async.wait_group 0;" ::: "memory"); }
        __syncthreads();

        const float* wb = swf + (t & 1) * 8192;
        float4 cb[8];
        #pragma unroll
        for (int u = 0; u < 8; u++)
            cb[u] = *(const float4*)&comb[g * 512 + t * 32 + u * 4];
        const float* cbs = (const float*)cb;
        #pragma unroll
        for (int k = 0; k < 32; k++) {
            float cv = cbs[k];
            float4 w = *(const float4*)&wb[k * 256 + c0];
            acc.x = fmaf(cv, w.x, acc.x);
            acc.y = fmaf(cv, w.y, acc.y);
            acc.z = fmaf(cv, w.z, acc.z);
            acc.w = fmaf(cv, w.w, acc.w);
        }
        __syncthreads();

        if (t + 2 < 16) {
            uint32_t dst = sbase + (uint32_t)((t & 1) * 32768);
            const float* src = Wpost + (size_t)(t + 2) * 32 * 256;
            #pragma unroll
            for (int i = 0; i < 8; i++) {
                int u = tid + i * 256;
                cp16(dst + (uint32_t)((u >> 6) * 1024 + (u & 63) * 16),
                     src + (size_t)(u >> 6) * 256 + (u & 63) * 4);
            }
            asm volatile("cp.async.commit_group;" ::: "memory");
        }
    }

    float4 bb = *(const float4*)&bpost[c0];
    float4 res = make_float4(acc.x + bb.x, acc.y + bb.y, acc.z + bb.z, acc.w + bb.w);
    *(float4*)&out[(size_t)(g0 + g) * HH + c0] = res;
}

// ---------------- launch ----------------
extern "C" void kernel_launch(void* const* d_in, const int* in_sizes, int n_in,
                              void* d_out, int out_size)
{
    const float* emb   = (const float*)d_in[0];
    const int*   batch = (const int*)  d_in[1];
    const float* props = (const float*)d_in[2];
    const int*   ntype = (const int*)  d_in[3];
    const float* Wpre  = (const float*)d_in[4];
    const float* bpre  = (const float*)d_in[5];
    const float* W1    = (const float*)d_in[6];
    const float* b1    = (const float*)d_in[7];
    const float* W2    = (const float*)d_in[8];
    const float* b2    = (const float*)d_in[9];
    const float* Wpost = (const float*)d_in[10];
    const float* bpost = (const float*)d_in[11];
    float* out = (float*)d_out;

    cudaFuncSetAttribute(main_kernel, cudaFuncAttributeMaxDynamicSharedMemorySize, SMEM_SZ);
    cudaFuncSetAttribute(final_kernel, cudaFuncAttributeMaxDynamicSharedMemorySize, FK_SMEM);

    void* p_sums = nullptr;
    void* p_maxs = nullptr;
    cudaGetSymbolAddress(&p_sums, g_sums);
    cudaGetSymbolAddress(&p_maxs, g_maxs);
    cudaMemsetAsync(p_sums, 0x00, NG * HH * sizeof(float));
    cudaMemsetAsync(p_maxs, 0xFF, NG * HH * sizeof(float));   // NaN -> acts as -inf for our atomics

    main_kernel<<<GRID_MAIN, 512, SMEM_SZ>>>(emb, batch, ntype, bpre, Wpre,
                                             props, W1, b1, W2, b2);
    final_kernel<<<NG / 4, 256, FK_SMEM>>>(Wpost, bpost, out);
}

// round 14
// speedup vs baseline: 1.4317x; 1.0227x over previous
#include <cuda_runtime.h>
#include <cuda_fp16.h>
#include <math.h>
#include <stdint.h>

#define NN   262144
#define HH   256
#define NV   65536
#define NG   512
#define NP   8
#define NHID 64

#define NTILES    4096      // NN / 64
#define GRID_MAIN 148

// ---------------- device globals ----------------
__device__ float  g_sums[NG * HH];
__device__ float  g_maxs[NG * HH];
__device__ int    g_start[NG + 1];

// ---------------- helpers ----------------
__device__ __forceinline__ uint32_t smem_u32(const void* p) {
    uint32_t a;
    asm("{ .reg .u64 t; cvta.to.shared.u64 t, %1; cvt.u32.u64 %0, t; }" : "=r"(a) : "l"(p));
    return a;
}
__device__ __forceinline__ void cp16(uint32_t dst, const void* src) {
    asm volatile("cp.async.cg.shared.global [%0], [%1], 16;" :: "r"(dst), "l"(src));
}
__device__ __forceinline__ void atomicMaxF(float* addr, float v) {
    if (v >= 0.0f) atomicMax((int*)addr, __float_as_int(v));
    else           atomicMin((unsigned int*)addr, __float_as_uint(v));
}
#define LDMX4(r0,r1,r2,r3,addr) \
    asm volatile("ldmatrix.sync.aligned.m8n8.x4.shared.b16 {%0,%1,%2,%3}, [%4];" \
                 : "=r"(r0), "=r"(r1), "=r"(r2), "=r"(r3) : "r"(addr))
#define MMA16816(c0,c1,c2,c3,a0,a1,a2,a3,b0,b1) \
    asm volatile("mma.sync.aligned.m16n8k16.row.col.f32.f16.f16.f32 " \
                 "{%0,%1,%2,%3}, {%4,%5,%6,%7}, {%8,%9}, {%0,%1,%2,%3};" \
                 : "+f"(c0), "+f"(c1), "+f"(c2), "+f"(c3) \
                 : "r"(a0), "r"(a1), "r"(a2), "r"(a3), "r"(b0), "r"(b1))

// ---------------- main: persistent HMMA GEMM; contiguous tiles; carry epilogue ----------------
// smem layout (206848 B dynamic):
//   B:        [0, 135168)                256 rows x 264 halfs (stride 528 B)
//   A stages: [135168, 135168+2*33792)   2 x (64 rows x 264 halfs)
//   misc at 202752:
//     brow[2][64] int (512) | wrow[2][64] f (512) | sbias[256] f (1024) | sgate[448] f (1792)
#define A_OFF    135168
#define A_STAGE  33792
#define MISC_OFF 202752
#define SMEM_SZ  206848

__global__ __launch_bounds__(512, 1) void main_kernel(
    const float* __restrict__ emb,
    const int*   __restrict__ batch,
    const int*   __restrict__ ntype,
    const float* __restrict__ bpre,
    const float* __restrict__ Wpre,
    const float* __restrict__ props,
    const float* __restrict__ W1, const float* __restrict__ b1,
    const float* __restrict__ W2, const float* __restrict__ b2)
{
    extern __shared__ char sm[];
    const uint32_t sbase = smem_u32(sm);
    int*   brow  = (int*)  (sm + MISC_OFF);            // [2][64]
    float* wrow  = (float*)(sm + MISC_OFF + 512);      // [2][64]
    float* sbias = (float*)(sm + MISC_OFF + 1024);     // [256]
    float* sgate = (float*)(sm + MISC_OFF + 2048);     // [448]

    const int tid  = threadIdx.x;
    const int wid  = tid >> 5;
    const int lane = tid & 31;
    const int wm   = wid >> 2;     // 0..3: rows [wm*16, +16)
    const int wn   = wid & 3;      // 0..3: cols [wn*64, +64)
    const int b    = blockIdx.x;

    // contiguous tile range: blocks 0..99 get 28 tiles, 100..147 get 27
    const int tstart = b * 27 + min(b, 100);
    const int tcnt   = 27 + (b < 100 ? 1 : 0);

    // ---- phase A: B transpose+convert, gates, g_start scan, sbias, A(tstart) LDG ----

    // B: Wpre[k][n] -> Bs[n][k] fp16 (coalesced LDG.32 across n at fixed k)
    {
        const int bn  = tid & 255;       // output row n
        const int bk0 = (tid >> 8) * 128;
        const uint32_t bdst = sbase + (uint32_t)(bn * 528 + bk0 * 2);
        #pragma unroll
        for (int jj = 0; jj < 16; jj++) {
            float v[8];
            #pragma unroll
            for (int i = 0; i < 8; i++)
                v[i] = __ldg(&Wpre[(size_t)(bk0 + jj * 8 + i) * 256 + bn]);
            __half2 q0 = __float22half2_rn(make_float2(v[0], v[1]));
            __half2 q1 = __float22half2_rn(make_float2(v[2], v[3]));
            __half2 q2 = __float22half2_rn(make_float2(v[4], v[5]));
            __half2 q3 = __float22half2_rn(make_float2(v[6], v[7]));
            asm volatile("st.shared.v4.b32 [%0], {%1,%2,%3,%4};"
                         :: "r"(bdst + jj * 16),
                            "r"(*(uint32_t*)&q0), "r"(*(uint32_t*)&q1),
                            "r"(*(uint32_t*)&q2), "r"(*(uint32_t*)&q3) : "memory");
        }
    }

    // gates for this CTA's contiguous var range
    {
        if (tid < tcnt * 16) {
            const int var = tstart * 16 + tid;
            float4 p0 = __ldg((const float4*)props + var * 2);
            float4 p1 = __ldg((const float4*)props + var * 2 + 1);
            float pr[NP] = {p0.x, p0.y, p0.z, p0.w, p1.x, p1.y, p1.z, p1.w};
            float accA = __ldg(b2), accB = 0.0f;
            #pragma unroll
            for (int jh = 0; jh < NHID; jh += 4) {
                float s0 = __ldg(b1 + jh),     s1 = __ldg(b1 + jh + 1);
                float s2 = __ldg(b1 + jh + 2), s3 = __ldg(b1 + jh + 3);
                #pragma unroll
                for (int p = 0; p < NP; p++) {
                    float pv = pr[p];
                    const float* w = W1 + p * NHID + jh;
                    s0 = fmaf(pv, __ldg(w),     s0);
                    s1 = fmaf(pv, __ldg(w + 1), s1);
                    s2 = fmaf(pv, __ldg(w + 2), s2);
                    s3 = fmaf(pv, __ldg(w + 3), s3);
                }
                accA = fmaf(fmaxf(s0, 0.0f), __ldg(W2 + jh),     accA);
                accB = fmaf(fmaxf(s1, 0.0f), __ldg(W2 + jh + 1), accB);
                accA = fmaf(fmaxf(s2, 0.0f), __ldg(W2 + jh + 2), accA);
                accB = fmaf(fmaxf(s3, 0.0f), __ldg(W2 + jh + 3), accB);
            }
            sgate[tid] = 1.0f / (1.0f + expf(-(accA + accB)));
        }
    }

    // segment boundary scan (first 65536 global threads, 4 nodes each)
    {
        int gid = b * 512 + tid;
        if (gid < NN / 4) {
            int i0 = gid * 4;
            int4 b4 = *(const int4*)&batch[i0];
            int v[4] = {b4.x, b4.y, b4.z, b4.w};
            int p = (i0 == 0) ? -1 : __ldg(&batch[i0 - 1]);
            #pragma unroll
            for (int e = 0; e < 4; e++) {
                for (int g = p + 1; g <= v[e]; g++) g_start[g] = i0 + e;
                p = v[e];
            }
            if (i0 + 4 == NN)
                for (int g = v[3] + 1; g <= NG; g++) g_start[g] = NN;
        }
    }

    if (tid < 256) sbias[tid] = bpre[tid];

    const int arow = tid >> 3;     // 0..63
    const int aseg = tid & 7;      // float4 slot
    const uint32_t a_sts0 = sbase + A_OFF + (uint32_t)((arow * 264 + aseg * 4) * 2);

    // A prefetch held as half2 (16 regs)
    uint32_t rh[16];
    {
        const float* ap = emb + (size_t)(tstart * 64 + arow) * HH + aseg * 4;
        #pragma unroll
        for (int j = 0; j < 8; j++) {
            float4 a = *(const float4*)(ap + j * 32);
            __half2 h0 = __float22half2_rn(make_float2(a.x, a.y));
            __half2 h1 = __float22half2_rn(make_float2(a.z, a.w));
            rh[2 * j]     = *(uint32_t*)&h0;
            rh[2 * j + 1] = *(uint32_t*)&h1;
        }
    }
    __syncthreads();

    // ---- phase B: A(tstart) STS, brow/wrow(tstart) ----
    #pragma unroll
    for (int j = 0; j < 8; j++) {
        asm volatile("st.shared.v2.b32 [%0], {%1,%2};"
                     :: "r"(a_sts0 + j * 64), "r"(rh[2 * j]), "r"(rh[2 * j + 1]) : "memory");
    }
    if (tid < 64) {
        int m = tstart * 64 + tid;
        brow[tid] = batch[m];
        wrow[tid] = (ntype[m] == 0) ? sgate[tid >> 2] : 1.0f;
    }
    __syncthreads();

    // ldmatrix lane addresses (stride 264 halfs -> conflict-free)
    const uint32_t a_lm = sbase + A_OFF +
        (uint32_t)(((wm * 16 + (lane & 15)) * 264 + (lane >> 4) * 8) * 2);
    const uint32_t b_lm = sbase +
        (uint32_t)(((wn * 64 + (lane >> 4) * 8 + (lane & 7)) * 264 + ((lane >> 3) & 1) * 8) * 2);

    // carry state
    int   carry_g = -1;
    float cs[8][2], cm[8][2];

    auto flush_carry = [&]() {
        #pragma unroll
        for (int ni = 0; ni < 8; ni++) {
            float s0 = cs[ni][0], s1 = cs[ni][1];
            float m0 = cm[ni][0], m1 = cm[ni][1];
            #pragma unroll
            for (int off = 4; off < 32; off <<= 1) {
                s0 += __shfl_xor_sync(0xffffffffu, s0, off);
                s1 += __shfl_xor_sync(0xffffffffu, s1, off);
                m0 = fmaxf(m0, __shfl_xor_sync(0xffffffffu, m0, off));
                m1 = fmaxf(m1, __shfl_xor_sync(0xffffffffu, m1, off));
            }
            if (lane < 4) {
                int c = wn * 64 + ni * 8 + lane * 2;
                atomicAdd(&g_sums[carry_g * HH + c],     s0);
                atomicAdd(&g_sums[carry_g * HH + c + 1], s1);
                atomicMaxF(&g_maxs[carry_g * HH + c],     m0);
                atomicMaxF(&g_maxs[carry_g * HH + c + 1], m1);
            }
        }
    };

    for (int it = 0; it < tcnt; it++) {
        const int cur = it & 1;
        const bool hn = (it + 1 < tcnt);
        const int nt  = tstart + it + 1;

        if (hn) {
            const float* ap = emb + (size_t)(nt * 64 + arow) * HH + aseg * 4;
            #pragma unroll
            for (int j = 0; j < 8; j++) {
                float4 a = *(const float4*)(ap + j * 32);
                __half2 h0 = __float22half2_rn(make_float2(a.x, a.y));
                __half2 h1 = __float22half2_rn(make_float2(a.z, a.w));
                rh[2 * j]     = *(uint32_t*)&h0;
                rh[2 * j + 1] = *(uint32_t*)&h1;
            }
            if (tid < 64) {
                int m = nt * 64 + tid;
                brow[(cur ^ 1) * 64 + tid] = batch[m];
                wrow[(cur ^ 1) * 64 + tid] =
                    (ntype[m] == 0) ? sgate[(it + 1) * 16 + (tid >> 2)] : 1.0f;
            }
        }

        float acc[8][4];
        #pragma unroll
        for (int ni = 0; ni < 8; ni++)
            #pragma unroll
            for (int r = 0; r < 4; r++) acc[ni][r] = 0.0f;

        const uint32_t ab = a_lm + (uint32_t)(cur * A_STAGE);
        #pragma unroll
        for (int ks = 0; ks < 16; ks++) {
            uint32_t af[4];
            LDMX4(af[0], af[1], af[2], af[3], ab + ks * 32);
            uint32_t bf[4][4];
            #pragma unroll
            for (int nip = 0; nip < 4; nip++)
                LDMX4(bf[nip][0], bf[nip][1], bf[nip][2], bf[nip][3],
                      b_lm + nip * 8448 + ks * 32);
            #pragma unroll
            for (int ni = 0; ni < 8; ni++)
                MMA16816(acc[ni][0], acc[ni][1], acc[ni][2], acc[ni][3],
                         af[0], af[1], af[2], af[3],
                         bf[ni >> 1][(ni & 1) * 2], bf[ni >> 1][(ni & 1) * 2 + 1]);
        }

        if (hn) {
            uint32_t base = sbase + A_OFF + (uint32_t)((cur ^ 1) * A_STAGE)
                          + (uint32_t)((arow * 264 + aseg * 4) * 2);
            #pragma unroll
            for (int j = 0; j < 8; j++) {
                asm volatile("st.shared.v2.b32 [%0], {%1,%2};"
                             :: "r"(base + j * 64), "r"(rh[2 * j]), "r"(rh[2 * j + 1]) : "memory");
            }
        }

        // ---- epilogue: bias + gate, carry-based segment reduce ----
        {
            const int l1 = wm * 16 + (lane >> 2);
            const int l2 = l1 + 8;
            const int*   br = brow + cur * 64;
            const float* wr = wrow + cur * 64;
            const float w1 = wr[l1], w2 = wr[l2];
            #pragma unroll
            for (int ni = 0; ni < 8; ni++) {
                int c = wn * 64 + ni * 8 + (lane & 3) * 2;
                float b0 = sbias[c], b1 = sbias[c + 1];
                acc[ni][0] = (acc[ni][0] + b0) * w1;
                acc[ni][1] = (acc[ni][1] + b1) * w1;
                acc[ni][2] = (acc[ni][2] + b0) * w2;
                acc[ni][3] = (acc[ni][3] + b1) * w2;
            }
            const int gtop = br[wm * 16];
            const int gbot = br[wm * 16 + 15];
            if (gtop == gbot) {
                if (gtop == carry_g) {
                    #pragma unroll
                    for (int ni = 0; ni < 8; ni++) {
                        cs[ni][0] += acc[ni][0] + acc[ni][2];
                        cs[ni][1] += acc[ni][1] + acc[ni][3];
                        cm[ni][0] = fmaxf(cm[ni][0], fmaxf(acc[ni][0], acc[ni][2]));
                        cm[ni][1] = fmaxf(cm[ni][1], fmaxf(acc[ni][1], acc[ni][3]));
                    }
                } else {
                    if (carry_g >= 0) flush_carry();
                    carry_g = gtop;
                    #pragma unroll
                    for (int ni = 0; ni < 8; ni++) {
                        cs[ni][0] = acc[ni][0] + acc[ni][2];
                        cs[ni][1] = acc[ni][1] + acc[ni][3];
                        cm[ni][0] = fmaxf(acc[ni][0], acc[ni][2]);
                        cm[ni][1] = fmaxf(acc[ni][1], acc[ni][3]);
                    }
                }
            } else {
                if (carry_g >= 0) flush_carry();
                carry_g = -1;
                const int bg1 = br[l1], bg2 = br[l2];
                for (int g = gtop; g <= gbot; g++) {
                    const bool p1 = (bg1 == g), p2 = (bg2 == g);
                    #pragma unroll
                    for (int ni = 0; ni < 8; ni++) {
                        float s0 = (p1 ? acc[ni][0] : 0.0f) + (p2 ? acc[ni][2] : 0.0f);
                        float s1 = (p1 ? acc[ni][1] : 0.0f) + (p2 ? acc[ni][3] : 0.0f);
                        float m0v = fmaxf(p1 ? acc[ni][0] : -INFINITY, p2 ? acc[ni][2] : -INFINITY);
                        float m1v = fmaxf(p1 ? acc[ni][1] : -INFINITY, p2 ? acc[ni][3] : -INFINITY);
                        #pragma unroll
                        for (int off = 4; off < 32; off <<= 1) {
                            s0  += __shfl_xor_sync(0xffffffffu, s0,  off);
                            s1  += __shfl_xor_sync(0xffffffffu, s1,  off);
                            m0v = fmaxf(m0v, __shfl_xor_sync(0xffffffffu, m0v, off));
                            m1v = fmaxf(m1v, __shfl_xor_sync(0xffffffffu, m1v, off));
                        }
                        if (lane < 4) {
                            int c = wn * 64 + ni * 8 + lane * 2;
                            atomicAdd(&g_sums[g * HH + c],     s0);
                            atomicAdd(&g_sums[g * HH + c + 1], s1);
                            if (m0v > -INFINITY) atomicMaxF(&g_maxs[g * HH + c],     m0v);
                            if (m1v > -INFINITY) atomicMaxF(&g_maxs[g * HH + c + 1], m1v);
                        }
                    }
                }
            }
        }
        __syncthreads();
    }

    if (carry_g >= 0) flush_carry();
}

// ---------------- final linear v3: 1 col/thread, graphs in registers ----------------
// dyn smem: sw 2 x (32 x 256 f) = 65536 | combT [512][4] f = 8192  -> 73728 B
#define FK_SMEM 73728

__global__ __launch_bounds__(256) void final_kernel(
    const float* __restrict__ Wpost,
    const float* __restrict__ bpost,
    float* __restrict__ out)
{
    extern __shared__ char fsm[];
    float* swf   = (float*)fsm;                 // [2][32][256]
    float* combT = (float*)(fsm + 65536);       // [512][4]
    const uint32_t sbase = smem_u32(fsm);

    const int tid = threadIdx.x;
    const int g0  = blockIdx.x * 4;

    // prologue: stage W k-tiles 0 and 1
    #pragma unroll
    for (int i = 0; i < 8; i++) {
        int u = tid + i * 256;
        cp16(sbase + (uint32_t)((u >> 6) * 1024 + (u & 63) * 16),
             Wpost + (size_t)(u >> 6) * 256 + (u & 63) * 4);
    }
    asm volatile("cp.async.commit_group;" ::: "memory");
    #pragma unroll
    for (int i = 0; i < 8; i++) {
        int u = tid + i * 256;
        cp16(sbase + 32768u + (uint32_t)((u >> 6) * 1024 + (u & 63) * 16),
             Wpost + (size_t)(32 + (u >> 6)) * 256 + (u & 63) * 4);
    }
    asm volatile("cp.async.commit_group;" ::: "memory");

    // fill combT[k][g] (invc computed inline)
    for (int idx = tid; idx < 2048; idx += 256) {
        int k = idx >> 2, g = idx & 3;
        int gg = g0 + g;
        float v;
        if (k < HH) {
            float cnt = (float)(g_start[gg + 1] - g_start[gg]);
            v = g_sums[(size_t)gg * HH + k] / fmaxf(cnt, 1.0f);
        } else {
            float m = g_maxs[(size_t)gg * HH + (k - HH)];
            v = isfinite(m) ? m : 0.0f;
        }
        combT[idx] = v;
    }

    const int c = tid;
    float a0 = 0.0f, a1 = 0.0f, a2 = 0.0f, a3 = 0.0f;

    for (int t = 0; t < 16; t++) {
        if (t < 15) { asm volatile("cp.async.wait_group 1;" ::: "memory"); }
        else        { asm volatile("cp.async.wait_group 0;" ::: "memory"); }
        __syncthreads();

        const float* wb = swf + (t & 1) * 8192;
        #pragma unroll
        for (int kk = 0; kk < 32; kk++) {
            float4 cb = *(const float4*)&combT[(t * 32 + kk) * 4];
            float w = wb[kk * 256 + c];
            a0 = fmaf(cb.x, w, a0);
            a1 = fmaf(cb.y, w, a1);
            a2 = fmaf(cb.z, w, a2);
            a3 = fmaf(cb.w, w, a3);
        }
        __syncthreads();

        if (t + 2 < 16) {
            uint32_t dst = sbase + (uint32_t)((t & 1) * 32768);
            const float* src = Wpost + (size_t)(t + 2) * 32 * 256;
            #pragma unroll
            for (int i = 0; i < 8; i++) {
                int u = tid + i * 256;
                cp16(dst + (uint32_t)((u >> 6) * 1024 + (u & 63) * 16),
                     src + (size_t)(u >> 6) * 256 + (u & 63) * 4);
            }
            asm volatile("cp.async.commit_group;" ::: "memory");
        }
    }

    float bb = bpost[c];
    out[(size_t)(g0 + 0) * HH + c] = a0 + bb;
    out[(size_t)(g0 + 1) * HH + c] = a1 + bb;
    out[(size_t)(g0 + 2) * HH + c] = a2 + bb;
    out[(size_t)(g0 + 3) * HH + c] = a3 + bb;
}

// ---------------- launch ----------------
extern "C" void kernel_launch(void* const* d_in, const int* in_sizes, int n_in,
                              void* d_out, int out_size)
{
    const float* emb   = (const float*)d_in[0];
    const int*   batch = (const int*)  d_in[1];
    const float* props = (const float*)d_in[2];
    const int*   ntype = (const int*)  d_in[3];
    const float* Wpre  = (const float*)d_in[4];
    const float* bpre  = (const float*)d_in[5];
    const float* W1    = (const float*)d_in[6];
    const float* b1    = (const float*)d_in[7];
    const float* W2    = (const float*)d_in[8];
    const float* b2    = (const float*)d_in[9];
    const float* Wpost = (const float*)d_in[10];
    const float* bpost = (const float*)d_in[11];
    float* out = (float*)d_out;

    cudaFuncSetAttribute(main_kernel, cudaFuncAttributeMaxDynamicSharedMemorySize, SMEM_SZ);
    cudaFuncSetAttribute(final_kernel, cudaFuncAttributeMaxDynamicSharedMemorySize, FK_SMEM);

    void* p_sums = nullptr;
    void* p_maxs = nullptr;
    cudaGetSymbolAddress(&p_sums, g_sums);
    cudaGetSymbolAddress(&p_maxs, g_maxs);
    cudaMemsetAsync(p_sums, 0x00, NG * HH * sizeof(float));
    cudaMemsetAsync(p_maxs, 0xFF, NG * HH * sizeof(float));   // NaN -> acts as -inf for our atomics

    main_kernel<<<GRID_MAIN, 512, SMEM_SZ>>>(emb, batch, ntype, bpre, Wpre,
                                             props, W1, b1, W2, b2);
    final_kernel<<<NG / 4, 256, FK_SMEM>>>(Wpost, bpost, out);
}